// round 1
// baseline (speedup 1.0000x reference)
#include <cuda_runtime.h>
#include <math.h>

#define DIM 1536
#define NH 12
#define HD 128
#define MAXS 2048
#define MAX_ATTN_W 32760
#define MT 64   // query tile
#define KT 48   // key tile

// scratch (allocation-free rule: __device__ globals)
__device__ float g_q[MAXS * DIM];
__device__ float g_k[MAXS * DIM];
__device__ float g_v[MAXS * DIM];
__device__ float g_o[MAXS * DIM];

// ---------------------------------------------------------------------------
// Y[m][n] = sum_k X[m][k] * W[n][k] + bias[n].  N = K = DIM.  (x @ W^T + b)
// 64x64 tile, BK=16, 256 threads, 4x4 micro-tile.
// ---------------------------------------------------------------------------
__global__ __launch_bounds__(256) void sgemm_nt(
    const float* __restrict__ X, const float* __restrict__ W,
    const float* __restrict__ bias, float* __restrict__ Y, int M)
{
    __shared__ float Xs[16][68];
    __shared__ float Ws[16][68];
    const int tx = threadIdx.x & 15;
    const int ty = threadIdx.x >> 4;
    const int m0 = blockIdx.x * 64;
    const int n0 = blockIdx.y * 64;
    const int lrow = threadIdx.x >> 2;        // 0..63
    const int lc4  = (threadIdx.x & 3) * 4;   // 0,4,8,12

    float acc[4][4];
#pragma unroll
    for (int i = 0; i < 4; i++)
#pragma unroll
        for (int j = 0; j < 4; j++) acc[i][j] = 0.0f;

    const bool xok = (m0 + lrow) < M;
    const float* Xp = X + (size_t)(m0 + lrow) * DIM + lc4;
    const float* Wp = W + (size_t)(n0 + lrow) * DIM + lc4;

    for (int k0 = 0; k0 < DIM; k0 += 16) {
        float4 xv = xok ? *(const float4*)(Xp + k0) : make_float4(0.f, 0.f, 0.f, 0.f);
        float4 wv = *(const float4*)(Wp + k0);
        Xs[lc4 + 0][lrow] = xv.x; Xs[lc4 + 1][lrow] = xv.y;
        Xs[lc4 + 2][lrow] = xv.z; Xs[lc4 + 3][lrow] = xv.w;
        Ws[lc4 + 0][lrow] = wv.x; Ws[lc4 + 1][lrow] = wv.y;
        Ws[lc4 + 2][lrow] = wv.z; Ws[lc4 + 3][lrow] = wv.w;
        __syncthreads();
#pragma unroll
        for (int kk = 0; kk < 16; kk++) {
            float4 a = *(const float4*)&Xs[kk][ty * 4];
            float4 b = *(const float4*)&Ws[kk][tx * 4];
            acc[0][0] += a.x * b.x; acc[0][1] += a.x * b.y; acc[0][2] += a.x * b.z; acc[0][3] += a.x * b.w;
            acc[1][0] += a.y * b.x; acc[1][1] += a.y * b.y; acc[1][2] += a.y * b.z; acc[1][3] += a.y * b.w;
            acc[2][0] += a.z * b.x; acc[2][1] += a.z * b.y; acc[2][2] += a.z * b.z; acc[2][3] += a.z * b.w;
            acc[3][0] += a.w * b.x; acc[3][1] += a.w * b.y; acc[3][2] += a.w * b.z; acc[3][3] += a.w * b.w;
        }
        __syncthreads();
    }

#pragma unroll
    for (int i = 0; i < 4; i++) {
        int m = m0 + ty * 4 + i;
        if (m < M) {
#pragma unroll
            for (int j = 0; j < 4; j++)
                Y[(size_t)m * DIM + n0 + tx * 4 + j] = acc[i][j] + bias[n0 + tx * 4 + j];
        }
    }
}

// ---------------------------------------------------------------------------
// Per-row RMSNorm (over DIM) followed by 3D causal RoPE per 128-d head.
// grid = (S, 2): y=0 -> q/gq, y=1 -> k/gk.  256 threads per block.
// ---------------------------------------------------------------------------
__global__ __launch_bounds__(256) void rmsnorm_rope(
    float* __restrict__ q, float* __restrict__ k,
    const float* __restrict__ gq, const float* __restrict__ gk,
    const float* __restrict__ freqs,
    const int* __restrict__ grid_sizes,
    const int* __restrict__ cur_start_p, int S)
{
    const int s = blockIdx.x;
    const int which = blockIdx.y;
    float* row = (which ? k : q) + (size_t)s * DIM;
    const float* g = which ? gk : gq;

    __shared__ float red[8];
    __shared__ float cs[64], sn[64];

    const int t = threadIdx.x;

    // sum of squares over the 1536-wide row
    float vals[6];
    float ss = 0.0f;
#pragma unroll
    for (int i = 0; i < 6; i++) {
        vals[i] = row[t + i * 256];
        ss += vals[i] * vals[i];
    }
#pragma unroll
    for (int o = 16; o; o >>= 1) ss += __shfl_xor_sync(0xffffffffu, ss, o);
    if ((t & 31) == 0) red[t >> 5] = ss;
    __syncthreads();
    if (t < 8) {
        float v = red[t];
#pragma unroll
        for (int o = 4; o; o >>= 1) v += __shfl_xor_sync(0xffu, v, o);
        if (t == 0) red[0] = v;
    }

    const int Hh = grid_sizes[1];
    const int Ww = grid_sizes[2];
    const int FHW = grid_sizes[0] * Hh * Ww;
    const bool rot = (s < FHW);

    if (rot && t < 64) {
        const int cur = cur_start_p[0];
        const int fs = Hh * Ww;
        const int sf = cur / fs;
        const int f = s / fs;
        const int rem = s - f * fs;
        const int h = rem / Ww;
        const int w = rem - h * Ww;
        int idx;
        if (t < 22)       idx = sf + f;
        else if (t < 43)  idx = h;
        else              idx = w;
        const float ang = freqs[idx * 64 + t];
        cs[t] = cosf(ang);
        sn[t] = sinf(ang);
    }
    __syncthreads();

    const float scale = rsqrtf(red[0] * (1.0f / DIM) + 1e-6f);

    if (rot) {
#pragma unroll
        for (int r = 0; r < 3; r++) {
            const int p = t + r * 256;       // pair index 0..767
            const int j = p & 63;
            const int e0 = 2 * p, e1 = 2 * p + 1;
            const float a = row[e0] * scale * g[e0];
            const float b = row[e1] * scale * g[e1];
            const float c = cs[j], s_ = sn[j];
            row[e0] = a * c - b * s_;
            row[e1] = a * s_ + b * c;
        }
    } else {
#pragma unroll
        for (int i = 0; i < 6; i++) {
            const int e = t + i * 256;
            row[e] = vals[i] * scale * g[e];
        }
    }
}

// ---------------------------------------------------------------------------
// Flash attention, fp32.  grid = (ceil(S/MT), NH).  256 threads.
// KV token tok: tok < cur_start -> from cache; else from freshly computed k/v.
// ---------------------------------------------------------------------------
__global__ __launch_bounds__(256, 2) void attention(
    const float* __restrict__ q,
    const float* __restrict__ knew, const float* __restrict__ vnew,
    const float* __restrict__ kcache, const float* __restrict__ vcache,
    float* __restrict__ o,
    const int* __restrict__ cur_start_p, int S)
{
    extern __shared__ float sm[];
    float (*Qs)[129] = (float(*)[129])sm;                                 // 64 x 129
    float (*Ks)[129] = (float(*)[129])(sm + MT * 129);                    // 48 x 129
    float (*Vs)[128] = (float(*)[128])(sm + MT * 129 + KT * 129);         // 48 x 128
    float (*Ps)[KT + 1] = (float(*)[KT + 1])(sm + MT * 129 + KT * 129 + KT * 128); // 64 x 49

    const int head = blockIdx.y;
    const int q0 = blockIdx.x * MT;
    const int t = threadIdx.x;
    const int tx = t & 15;
    const int ty = t >> 4;

    const int cur = cur_start_p[0];
    const int cur_end = cur + S;
    int win_start = cur_end - MAX_ATTN_W;
    if (win_start < 0) win_start = 0;
    const int Lw = cur_end - win_start;

    // load Q tile (rows beyond S -> 0)
    for (int i = t; i < MT * 32; i += 256) {
        const int r = i >> 5, c4 = (i & 31) * 4;
        float4 v = make_float4(0.f, 0.f, 0.f, 0.f);
        const int gr = q0 + r;
        if (gr < S) v = *(const float4*)&q[(size_t)gr * DIM + head * HD + c4];
        Qs[r][c4 + 0] = v.x; Qs[r][c4 + 1] = v.y; Qs[r][c4 + 2] = v.z; Qs[r][c4 + 3] = v.w;
    }

    float m_i[4], l_i[4], O[4][8];
#pragma unroll
    for (int i = 0; i < 4; i++) {
        m_i[i] = -1e30f;
        l_i[i] = 0.0f;
#pragma unroll
        for (int c = 0; c < 8; c++) O[i][c] = 0.0f;
    }

    const int ntiles = (Lw + KT - 1) / KT;
    const float sc = 0.08838834764831845f;  // 1/sqrt(128)

    for (int tile = 0; tile < ntiles; tile++) {
        const int kbase = win_start + tile * KT;
        __syncthreads();  // protects Ks/Vs/Qs before (re)filling
        for (int i = t; i < KT * 32; i += 256) {
            const int r = i >> 5, c4 = (i & 31) * 4;
            const int tok = kbase + r;
            float4 kv = make_float4(0.f, 0.f, 0.f, 0.f);
            float4 vv = make_float4(0.f, 0.f, 0.f, 0.f);
            if (tok < cur_end) {
                if (tok < cur) {
                    const size_t off = ((size_t)tok * NH + head) * HD + c4;
                    kv = *(const float4*)&kcache[off];
                    vv = *(const float4*)&vcache[off];
                } else {
                    const size_t off = (size_t)(tok - cur) * DIM + head * HD + c4;
                    kv = *(const float4*)&knew[off];
                    vv = *(const float4*)&vnew[off];
                }
            }
            Ks[r][c4 + 0] = kv.x; Ks[r][c4 + 1] = kv.y; Ks[r][c4 + 2] = kv.z; Ks[r][c4 + 3] = kv.w;
            *(float4*)&Vs[r][c4] = vv;
        }
        __syncthreads();

        // S tile = Q K^T : rows ty*4..+3, cols tx*3..+2
        float sacc[4][3];
#pragma unroll
        for (int i = 0; i < 4; i++)
#pragma unroll
            for (int j = 0; j < 3; j++) sacc[i][j] = 0.0f;

#pragma unroll 8
        for (int kk = 0; kk < HD; kk++) {
            const float a0 = Qs[ty * 4 + 0][kk];
            const float a1 = Qs[ty * 4 + 1][kk];
            const float a2 = Qs[ty * 4 + 2][kk];
            const float a3 = Qs[ty * 4 + 3][kk];
            const float b0 = Ks[tx * 3 + 0][kk];
            const float b1 = Ks[tx * 3 + 1][kk];
            const float b2 = Ks[tx * 3 + 2][kk];
            sacc[0][0] += a0 * b0; sacc[0][1] += a0 * b1; sacc[0][2] += a0 * b2;
            sacc[1][0] += a1 * b0; sacc[1][1] += a1 * b1; sacc[1][2] += a1 * b2;
            sacc[2][0] += a2 * b0; sacc[2][1] += a2 * b1; sacc[2][2] += a2 * b2;
            sacc[3][0] += a3 * b0; sacc[3][1] += a3 * b1; sacc[3][2] += a3 * b2;
        }

        // scale + mask out-of-window columns
#pragma unroll
        for (int j = 0; j < 3; j++) {
            const int col = tile * KT + tx * 3 + j;
            const bool ok = col < Lw;
#pragma unroll
            for (int i = 0; i < 4; i++)
                sacc[i][j] = ok ? sacc[i][j] * sc : -1e30f;
        }

        // online softmax, row stats duplicated across the 16-lane row group
#pragma unroll
        for (int i = 0; i < 4; i++) {
            float rmax = fmaxf(fmaxf(sacc[i][0], sacc[i][1]), sacc[i][2]);
#pragma unroll
            for (int off = 8; off; off >>= 1)
                rmax = fmaxf(rmax, __shfl_xor_sync(0xffffffffu, rmax, off));
            const float newm = fmaxf(m_i[i], rmax);
            const float alpha = __expf(m_i[i] - newm);
            const float p0 = __expf(sacc[i][0] - newm);
            const float p1 = __expf(sacc[i][1] - newm);
            const float p2 = __expf(sacc[i][2] - newm);
            float rsum = p0 + p1 + p2;
#pragma unroll
            for (int off = 8; off; off >>= 1)
                rsum += __shfl_xor_sync(0xffffffffu, rsum, off);
            l_i[i] = l_i[i] * alpha + rsum;
            m_i[i] = newm;
#pragma unroll
            for (int c = 0; c < 8; c++) O[i][c] *= alpha;
            Ps[ty * 4 + i][tx * 3 + 0] = p0;
            Ps[ty * 4 + i][tx * 3 + 1] = p1;
            Ps[ty * 4 + i][tx * 3 + 2] = p2;
        }
        __syncthreads();

        // O += P V : rows ty*4..+3, cols tx*8..+7
#pragma unroll 4
        for (int tt = 0; tt < KT; tt++) {
            const float a0 = Ps[ty * 4 + 0][tt];
            const float a1 = Ps[ty * 4 + 1][tt];
            const float a2 = Ps[ty * 4 + 2][tt];
            const float a3 = Ps[ty * 4 + 3][tt];
            const float4 b0 = *(const float4*)&Vs[tt][tx * 8];
            const float4 b1 = *(const float4*)&Vs[tt][tx * 8 + 4];
            O[0][0] += a0 * b0.x; O[0][1] += a0 * b0.y; O[0][2] += a0 * b0.z; O[0][3] += a0 * b0.w;
            O[0][4] += a0 * b1.x; O[0][5] += a0 * b1.y; O[0][6] += a0 * b1.z; O[0][7] += a0 * b1.w;
            O[1][0] += a1 * b0.x; O[1][1] += a1 * b0.y; O[1][2] += a1 * b0.z; O[1][3] += a1 * b0.w;
            O[1][4] += a1 * b1.x; O[1][5] += a1 * b1.y; O[1][6] += a1 * b1.z; O[1][7] += a1 * b1.w;
            O[2][0] += a2 * b0.x; O[2][1] += a2 * b0.y; O[2][2] += a2 * b0.z; O[2][3] += a2 * b0.w;
            O[2][4] += a2 * b1.x; O[2][5] += a2 * b1.y; O[2][6] += a2 * b1.z; O[2][7] += a2 * b1.w;
            O[3][0] += a3 * b0.x; O[3][1] += a3 * b0.y; O[3][2] += a3 * b0.z; O[3][3] += a3 * b0.w;
            O[3][4] += a3 * b1.x; O[3][5] += a3 * b1.y; O[3][6] += a3 * b1.z; O[3][7] += a3 * b1.w;
        }
    }

    // write normalized output
#pragma unroll
    for (int i = 0; i < 4; i++) {
        const int gr = q0 + ty * 4 + i;
        if (gr < S) {
            const float inv = 1.0f / l_i[i];
#pragma unroll
            for (int c = 0; c < 8; c++)
                o[(size_t)gr * DIM + head * HD + tx * 8 + c] = O[i][c] * inv;
        }
    }
}

// ---------------------------------------------------------------------------
extern "C" void kernel_launch(void* const* d_in, const int* in_sizes, int n_in,
                              void* d_out, int out_size)
{
    const float* x      = (const float*)d_in[0];
    const float* freqs  = (const float*)d_in[1];
    const float* wq     = (const float*)d_in[2];
    const float* bq     = (const float*)d_in[3];
    const float* wk     = (const float*)d_in[4];
    const float* bk     = (const float*)d_in[5];
    const float* wv     = (const float*)d_in[6];
    const float* bv     = (const float*)d_in[7];
    const float* wo     = (const float*)d_in[8];
    const float* bo     = (const float*)d_in[9];
    const float* gq     = (const float*)d_in[10];
    const float* gk     = (const float*)d_in[11];
    const float* kcache = (const float*)d_in[12];
    const float* vcache = (const float*)d_in[13];
    const int* grid_sizes = (const int*)d_in[14];
    const int* cur_start  = (const int*)d_in[16];

    const int S = in_sizes[0] / DIM;

    float *q, *k, *v, *o;
    cudaGetSymbolAddress((void**)&q, g_q);
    cudaGetSymbolAddress((void**)&k, g_k);
    cudaGetSymbolAddress((void**)&v, g_v);
    cudaGetSymbolAddress((void**)&o, g_o);

    dim3 gg((S + 63) / 64, DIM / 64);
    sgemm_nt<<<gg, 256>>>(x, wq, bq, q, S);
    sgemm_nt<<<gg, 256>>>(x, wk, bk, k, S);
    sgemm_nt<<<gg, 256>>>(x, wv, bv, v, S);

    rmsnorm_rope<<<dim3(S, 2), 256>>>(q, k, gq, gk, freqs, grid_sizes, cur_start, S);

    const size_t smem = (size_t)(MT * 129 + KT * 129 + KT * 128 + MT * (KT + 1)) * sizeof(float);
    cudaFuncSetAttribute(attention, cudaFuncAttributeMaxDynamicSharedMemorySize, (int)smem);
    attention<<<dim3((S + MT - 1) / MT, NH), 256, smem>>>(q, k, v, kcache, vcache, o, cur_start, S);

    sgemm_nt<<<gg, 256>>>(o, wo, bo, (float*)d_out, S);
}

// round 3
// speedup vs baseline: 1.9703x; 1.9703x over previous
#include <cuda_runtime.h>
#include <math.h>
#include <stdint.h>

#define DIM 1536
#define NH 12
#define HD 128
#define MAXS 2048
#define MAX_ATTN_W 32760

// attention tiles
#define AMT 64       // query rows per CTA
#define AKT 64       // keys per tile
// smem row strides (words) chosen so fragment reads are bank-conflict-free
#define KS_STR 132   // mod 32 == 4
#define VS_STR 136   // mod 32 == 8
#define PS_STR 68    // mod 32 == 4

// GEMM tiles
#define BM 128
#define BN 128
#define BK 32
#define XS_STR 36    // mod 32 == 4

__device__ float g_q[MAXS * DIM];
__device__ float g_k[MAXS * DIM];
__device__ float g_v[MAXS * DIM];
__device__ float g_o[MAXS * DIM];

__device__ __forceinline__ uint32_t f2tf32(float x) {
    uint32_t u;
    asm("cvt.rna.tf32.f32 %0, %1;" : "=r"(u) : "f"(x));
    return u;
}

// D += A*B  (m16n8k8, tf32 inputs as b32 regs, f32 accum)
__device__ __forceinline__ void mma8(float* d, const uint32_t* a, const uint32_t* b) {
    asm volatile(
        "mma.sync.aligned.m16n8k8.row.col.f32.tf32.tf32.f32 "
        "{%0,%1,%2,%3}, {%4,%5,%6,%7}, {%8,%9}, {%0,%1,%2,%3};"
        : "+f"(d[0]), "+f"(d[1]), "+f"(d[2]), "+f"(d[3])
        : "r"(a[0]), "r"(a[1]), "r"(a[2]), "r"(a[3]), "r"(b[0]), "r"(b[1]));
}

// ---------------------------------------------------------------------------
// tf32 mma.sync GEMM: Y[m][n] = sum_k X[m][k]*W[n][k] + bias[n]
// 128x128 CTA, 256 threads, warp tile 32(m) x 64(n).
// blockIdx.z picks (W,B,Y) set (fused QKV).
// ---------------------------------------------------------------------------
__global__ __launch_bounds__(256, 2) void gemm_mma(
    const float* __restrict__ X,
    const float* __restrict__ W0, const float* __restrict__ B0, float* __restrict__ Y0,
    const float* __restrict__ W1, const float* __restrict__ B1, float* __restrict__ Y1,
    const float* __restrict__ W2, const float* __restrict__ B2, float* __restrict__ Y2,
    int M)
{
    __shared__ uint32_t Xs[BM][XS_STR];
    __shared__ uint32_t Ws[BN][XS_STR];

    const float* W; const float* Bi; float* Y;
    if (blockIdx.z == 0)      { W = W0; Bi = B0; Y = Y0; }
    else if (blockIdx.z == 1) { W = W1; Bi = B1; Y = Y1; }
    else                      { W = W2; Bi = B2; Y = Y2; }

    const int t   = threadIdx.x;
    const int l   = t & 31;
    const int wid = t >> 5;
    const int wm  = (wid & 3) * 32;   // warp m offset
    const int wn  = (wid >> 2) * 64;  // warp n offset
    const int g   = l >> 2;           // groupID
    const int tg  = l & 3;            // thread in group
    const int m0  = blockIdx.x * BM;
    const int n0  = blockIdx.y * BN;

    const int lr = t >> 3;            // 0..31 load row
    const int ls = (t & 7) * 4;       // load col (floats)

    float acc[2][8][4];
#pragma unroll
    for (int i = 0; i < 2; i++)
#pragma unroll
        for (int j = 0; j < 8; j++)
#pragma unroll
            for (int c = 0; c < 4; c++) acc[i][j][c] = 0.0f;

    for (int c = 0; c < DIM / BK; c++) {
        __syncthreads();
        // stage 128x32 of X and W (4 rows-per-iter x 32 iters over 256 thr)
#pragma unroll
        for (int it = 0; it < 4; it++) {
            const int r = lr + it * 32;
            float4 xv = make_float4(0.f, 0.f, 0.f, 0.f);
            if (m0 + r < M) xv = *(const float4*)&X[(size_t)(m0 + r) * DIM + c * BK + ls];
            Xs[r][ls + 0] = f2tf32(xv.x); Xs[r][ls + 1] = f2tf32(xv.y);
            Xs[r][ls + 2] = f2tf32(xv.z); Xs[r][ls + 3] = f2tf32(xv.w);
            float4 wv = *(const float4*)&W[(size_t)(n0 + r) * DIM + c * BK + ls];
            Ws[r][ls + 0] = f2tf32(wv.x); Ws[r][ls + 1] = f2tf32(wv.y);
            Ws[r][ls + 2] = f2tf32(wv.z); Ws[r][ls + 3] = f2tf32(wv.w);
        }
        __syncthreads();

#pragma unroll
        for (int ks = 0; ks < 4; ks++) {
            const int k = ks * 8;
            uint32_t afr[2][4];
#pragma unroll
            for (int mt = 0; mt < 2; mt++) {
                const int r = wm + mt * 16 + g;
                afr[mt][0] = Xs[r][k + tg];
                afr[mt][1] = Xs[r + 8][k + tg];
                afr[mt][2] = Xs[r][k + 4 + tg];
                afr[mt][3] = Xs[r + 8][k + 4 + tg];
            }
#pragma unroll
            for (int nt = 0; nt < 8; nt++) {
                uint32_t bfr[2];
                const int n = wn + nt * 8 + g;
                bfr[0] = Ws[n][k + tg];
                bfr[1] = Ws[n][k + 4 + tg];
                mma8(acc[0][nt], afr[0], bfr);
                mma8(acc[1][nt], afr[1], bfr);
            }
        }
    }

    // epilogue: c0/c1 -> (row, 2tg), (row, 2tg+1); c2/c3 -> row+8
#pragma unroll
    for (int mt = 0; mt < 2; mt++) {
        const int r0 = m0 + wm + mt * 16 + g;
#pragma unroll
        for (int nt = 0; nt < 8; nt++) {
            const int cc = n0 + wn + nt * 8 + 2 * tg;
            const float b0 = Bi[cc], b1 = Bi[cc + 1];
            if (r0 < M) {
                float2 v = make_float2(acc[mt][nt][0] + b0, acc[mt][nt][1] + b1);
                *(float2*)&Y[(size_t)r0 * DIM + cc] = v;
            }
            if (r0 + 8 < M) {
                float2 v = make_float2(acc[mt][nt][2] + b0, acc[mt][nt][3] + b1);
                *(float2*)&Y[(size_t)(r0 + 8) * DIM + cc] = v;
            }
        }
    }
}

// ---------------------------------------------------------------------------
// RMSNorm + 3D causal RoPE (unchanged from R1)
// ---------------------------------------------------------------------------
__global__ __launch_bounds__(256) void rmsnorm_rope(
    float* __restrict__ q, float* __restrict__ k,
    const float* __restrict__ gq, const float* __restrict__ gk,
    const float* __restrict__ freqs,
    const int* __restrict__ grid_sizes,
    const int* __restrict__ cur_start_p, int S)
{
    const int s = blockIdx.x;
    const int which = blockIdx.y;
    float* row = (which ? k : q) + (size_t)s * DIM;
    const float* g = which ? gk : gq;

    __shared__ float red[8];
    __shared__ float cs[64], sn[64];
    const int t = threadIdx.x;

    float vals[6];
    float ss = 0.0f;
#pragma unroll
    for (int i = 0; i < 6; i++) {
        vals[i] = row[t + i * 256];
        ss += vals[i] * vals[i];
    }
#pragma unroll
    for (int o = 16; o; o >>= 1) ss += __shfl_xor_sync(0xffffffffu, ss, o);
    if ((t & 31) == 0) red[t >> 5] = ss;
    __syncthreads();
    if (t < 8) {
        float v = red[t];
#pragma unroll
        for (int o = 4; o; o >>= 1) v += __shfl_xor_sync(0xffu, v, o);
        if (t == 0) red[0] = v;
    }

    const int Hh = grid_sizes[1];
    const int Ww = grid_sizes[2];
    const int FHW = grid_sizes[0] * Hh * Ww;
    const bool rot = (s < FHW);

    if (rot && t < 64) {
        const int cur = cur_start_p[0];
        const int fs = Hh * Ww;
        const int sf = cur / fs;
        const int f = s / fs;
        const int rem = s - f * fs;
        const int h = rem / Ww;
        const int w = rem - h * Ww;
        int idx;
        if (t < 22)       idx = sf + f;
        else if (t < 43)  idx = h;
        else              idx = w;
        const float ang = freqs[idx * 64 + t];
        cs[t] = cosf(ang);
        sn[t] = sinf(ang);
    }
    __syncthreads();

    const float scale = rsqrtf(red[0] * (1.0f / DIM) + 1e-6f);

    if (rot) {
#pragma unroll
        for (int r = 0; r < 3; r++) {
            const int p = t + r * 256;
            const int j = p & 63;
            const int e0 = 2 * p, e1 = 2 * p + 1;
            const float a = row[e0] * scale * g[e0];
            const float b = row[e1] * scale * g[e1];
            const float c = cs[j], s_ = sn[j];
            row[e0] = a * c - b * s_;
            row[e1] = a * s_ + b * c;
        }
    } else {
#pragma unroll
        for (int i = 0; i < 6; i++) {
            const int e = t + i * 256;
            row[e] = vals[i] * scale * g[e];
        }
    }
}

// ---------------------------------------------------------------------------
// Flash attention on tf32 mma.sync.  4 warps; warp w owns q rows [16w,16w+16).
// grid = (ceil(S/64), NH), 128 threads.
// ---------------------------------------------------------------------------
__global__ __launch_bounds__(128, 2) void attention(
    const float* __restrict__ q,
    const float* __restrict__ knew, const float* __restrict__ vnew,
    const float* __restrict__ kcache, const float* __restrict__ vcache,
    float* __restrict__ o,
    const int* __restrict__ cur_start_p, int S)
{
    extern __shared__ uint32_t sm[];
    uint32_t* Ks = sm;                                  // [AKT][KS_STR]
    uint32_t* Vs = sm + AKT * KS_STR;                   // [AKT][VS_STR]
    uint32_t* Ps = sm + AKT * KS_STR + AKT * VS_STR;    // [AMT][PS_STR]

    const int head = blockIdx.y;
    const int q0 = blockIdx.x * AMT;
    const int t = threadIdx.x;
    const int l = t & 31;
    const int wid = t >> 5;
    const int g = l >> 2;
    const int tg = l & 3;

    const int cur = cur_start_p[0];
    const int cur_end = cur + S;
    int win_start = cur_end - MAX_ATTN_W;
    if (win_start < 0) win_start = 0;
    const int Lw = cur_end - win_start;

    // preload Q A-fragments for this warp's 16 rows (16 ksteps x 4 regs)
    const int row0 = q0 + wid * 16 + g;
    const size_t qb0 = (size_t)row0 * DIM + head * HD;
    const size_t qb1 = (size_t)(row0 + 8) * DIM + head * HD;
    const bool r0ok = row0 < S, r1ok = (row0 + 8) < S;
    uint32_t qa[16][4];
#pragma unroll
    for (int ks = 0; ks < 16; ks++) {
        const int k = ks * 8 + tg;
        qa[ks][0] = r0ok ? f2tf32(q[qb0 + k])     : 0u;
        qa[ks][1] = r1ok ? f2tf32(q[qb1 + k])     : 0u;
        qa[ks][2] = r0ok ? f2tf32(q[qb0 + k + 4]) : 0u;
        qa[ks][3] = r1ok ? f2tf32(q[qb1 + k + 4]) : 0u;
    }

    float o_acc[16][4];
#pragma unroll
    for (int nt = 0; nt < 16; nt++)
#pragma unroll
        for (int c = 0; c < 4; c++) o_acc[nt][c] = 0.0f;
    float mA = -1e30f, mB = -1e30f, lA = 0.0f, lB = 0.0f;

    const int ntiles = (Lw + AKT - 1) / AKT;
    const float sc = 0.08838834764831845f;

    for (int tile = 0; tile < ntiles; tile++) {
        const int kbase = win_start + tile * AKT;
        __syncthreads();
        // stage K,V (64 tokens x 128 dims), tf32-converted
        for (int i = t; i < AKT * 32; i += 128) {
            const int r = i >> 5, c4 = (i & 31) * 4;
            const int tok = kbase + r;
            float4 kv = make_float4(0.f, 0.f, 0.f, 0.f);
            float4 vv = make_float4(0.f, 0.f, 0.f, 0.f);
            if (tok < cur_end) {
                if (tok < cur) {
                    const size_t off = ((size_t)tok * NH + head) * HD + c4;
                    kv = *(const float4*)&kcache[off];
                    vv = *(const float4*)&vcache[off];
                } else {
                    const size_t off = (size_t)(tok - cur) * DIM + head * HD + c4;
                    kv = *(const float4*)&knew[off];
                    vv = *(const float4*)&vnew[off];
                }
            }
            uint32_t* kr = Ks + r * KS_STR + c4;
            kr[0] = f2tf32(kv.x); kr[1] = f2tf32(kv.y); kr[2] = f2tf32(kv.z); kr[3] = f2tf32(kv.w);
            uint32_t* vr = Vs + r * VS_STR + c4;
            vr[0] = f2tf32(vv.x); vr[1] = f2tf32(vv.y); vr[2] = f2tf32(vv.z); vr[3] = f2tf32(vv.w);
        }
        __syncthreads();

        // S = Q K^T  (8 n-tiles of 8 keys)
        float s_acc[8][4];
#pragma unroll
        for (int nt = 0; nt < 8; nt++)
#pragma unroll
            for (int c = 0; c < 4; c++) s_acc[nt][c] = 0.0f;

#pragma unroll 4
        for (int ks = 0; ks < 16; ks++) {
            const int k = ks * 8 + tg;
#pragma unroll
            for (int nt = 0; nt < 8; nt++) {
                uint32_t bfr[2];
                const uint32_t* kp = Ks + (nt * 8 + g) * KS_STR + k;
                bfr[0] = kp[0];
                bfr[1] = kp[4];
                mma8(s_acc[nt], qa[ks], bfr);
            }
        }

        // scale + mask
#pragma unroll
        for (int nt = 0; nt < 8; nt++) {
            const int key0 = kbase + nt * 8 + 2 * tg;
            const bool ok0 = key0 < cur_end, ok1 = (key0 + 1) < cur_end;
            s_acc[nt][0] = ok0 ? s_acc[nt][0] * sc : -1e30f;
            s_acc[nt][1] = ok1 ? s_acc[nt][1] * sc : -1e30f;
            s_acc[nt][2] = ok0 ? s_acc[nt][2] * sc : -1e30f;
            s_acc[nt][3] = ok1 ? s_acc[nt][3] * sc : -1e30f;
        }

        // online softmax (rows A: c0/c1, rows B: c2/c3); 4 lanes share a row
        float rmA = -1e30f, rmB = -1e30f;
#pragma unroll
        for (int nt = 0; nt < 8; nt++) {
            rmA = fmaxf(rmA, fmaxf(s_acc[nt][0], s_acc[nt][1]));
            rmB = fmaxf(rmB, fmaxf(s_acc[nt][2], s_acc[nt][3]));
        }
        rmA = fmaxf(rmA, __shfl_xor_sync(0xffffffffu, rmA, 1));
        rmA = fmaxf(rmA, __shfl_xor_sync(0xffffffffu, rmA, 2));
        rmB = fmaxf(rmB, __shfl_xor_sync(0xffffffffu, rmB, 1));
        rmB = fmaxf(rmB, __shfl_xor_sync(0xffffffffu, rmB, 2));
        const float nmA = fmaxf(mA, rmA), nmB = fmaxf(mB, rmB);
        const float aA = __expf(mA - nmA), aB = __expf(mB - nmB);
        mA = nmA; mB = nmB;

        float sumA = 0.0f, sumB = 0.0f;
        uint32_t* pr0 = Ps + (wid * 16 + g) * PS_STR + 2 * tg;
        uint32_t* pr1 = pr0 + 8 * PS_STR;
#pragma unroll
        for (int nt = 0; nt < 8; nt++) {
            const float p0 = __expf(s_acc[nt][0] - nmA);
            const float p1 = __expf(s_acc[nt][1] - nmA);
            const float p2 = __expf(s_acc[nt][2] - nmB);
            const float p3 = __expf(s_acc[nt][3] - nmB);
            sumA += p0 + p1; sumB += p2 + p3;
            pr0[nt * 8 + 0] = f2tf32(p0); pr0[nt * 8 + 1] = f2tf32(p1);
            pr1[nt * 8 + 0] = f2tf32(p2); pr1[nt * 8 + 1] = f2tf32(p3);
        }
        sumA += __shfl_xor_sync(0xffffffffu, sumA, 1);
        sumA += __shfl_xor_sync(0xffffffffu, sumA, 2);
        sumB += __shfl_xor_sync(0xffffffffu, sumB, 1);
        sumB += __shfl_xor_sync(0xffffffffu, sumB, 2);
        lA = lA * aA + sumA;
        lB = lB * aB + sumB;

#pragma unroll
        for (int nt = 0; nt < 16; nt++) {
            o_acc[nt][0] *= aA; o_acc[nt][1] *= aA;
            o_acc[nt][2] *= aB; o_acc[nt][3] *= aB;
        }
        __syncwarp();

        // O += P V   (A = P rows of this warp, B = V)
#pragma unroll 2
        for (int ks = 0; ks < 8; ks++) {
            const int k = ks * 8 + tg;
            uint32_t afr[4];
            const uint32_t* pp = Ps + (wid * 16 + g) * PS_STR + k;
            afr[0] = pp[0];
            afr[1] = pp[8 * PS_STR];
            afr[2] = pp[4];
            afr[3] = pp[8 * PS_STR + 4];
#pragma unroll
            for (int nt = 0; nt < 16; nt++) {
                uint32_t bfr[2];
                const uint32_t* vp = Vs + k * VS_STR + nt * 8 + g;
                bfr[0] = vp[0];
                bfr[1] = vp[4 * VS_STR];
                mma8(o_acc[nt], afr, bfr);
            }
        }
        __syncwarp();
    }

    // write normalized output
    const float iA = 1.0f / lA, iB = 1.0f / lB;
#pragma unroll
    for (int nt = 0; nt < 16; nt++) {
        const int cc = head * HD + nt * 8 + 2 * tg;
        if (r0ok) {
            float2 v = make_float2(o_acc[nt][0] * iA, o_acc[nt][1] * iA);
            *(float2*)&o[(size_t)row0 * DIM + cc] = v;
        }
        if (r1ok) {
            float2 v = make_float2(o_acc[nt][2] * iB, o_acc[nt][3] * iB);
            *(float2*)&o[(size_t)(row0 + 8) * DIM + cc] = v;
        }
    }
}

// ---------------------------------------------------------------------------
extern "C" void kernel_launch(void* const* d_in, const int* in_sizes, int n_in,
                              void* d_out, int out_size)
{
    const float* x      = (const float*)d_in[0];
    const float* freqs  = (const float*)d_in[1];
    const float* wq     = (const float*)d_in[2];
    const float* bq     = (const float*)d_in[3];
    const float* wk     = (const float*)d_in[4];
    const float* bk     = (const float*)d_in[5];
    const float* wv     = (const float*)d_in[6];
    const float* bv     = (const float*)d_in[7];
    const float* wo     = (const float*)d_in[8];
    const float* bo     = (const float*)d_in[9];
    const float* gq     = (const float*)d_in[10];
    const float* gk     = (const float*)d_in[11];
    const float* kcache = (const float*)d_in[12];
    const float* vcache = (const float*)d_in[13];
    const int* grid_sizes = (const int*)d_in[14];
    const int* cur_start  = (const int*)d_in[16];

    const int S = in_sizes[0] / DIM;

    float *q, *k, *v, *o;
    cudaGetSymbolAddress((void**)&q, g_q);
    cudaGetSymbolAddress((void**)&k, g_k);
    cudaGetSymbolAddress((void**)&v, g_v);
    cudaGetSymbolAddress((void**)&o, g_o);

    // fused QKV projections
    gemm_mma<<<dim3((S + BM - 1) / BM, DIM / BN, 3), 256>>>(
        x, wq, bq, q, wk, bk, k, wv, bv, v, S);

    rmsnorm_rope<<<dim3(S, 2), 256>>>(q, k, gq, gk, freqs, grid_sizes, cur_start, S);

    const int asmem = (AKT * KS_STR + AKT * VS_STR + AMT * PS_STR) * 4;  // 86016
    cudaFuncSetAttribute(attention, cudaFuncAttributeMaxDynamicSharedMemorySize, asmem);
    attention<<<dim3((S + AMT - 1) / AMT, NH), 128, asmem>>>(
        q, k, v, kcache, vcache, o, cur_start, S);

    // output projection
    gemm_mma<<<dim3((S + BM - 1) / BM, DIM / BN, 1), 256>>>(
        o, wo, bo, (float*)d_out, wo, bo, (float*)d_out, wo, bo, (float*)d_out, S);
}

// round 4
// speedup vs baseline: 1.9751x; 1.0025x over previous
#include <cuda_runtime.h>
#include <math.h>
#include <stdint.h>

#define DIM 1536
#define NH 12
#define HD 128
#define MAXS 2048
#define MAX_ATTN_W 32760

// attention tiles
#define AMT 64       // query rows per CTA
#define AKT 64       // keys per tile
// smem row strides (words) chosen so fragment reads are bank-conflict-free
#define KS_STR 132   // mod 32 == 4
#define VS_STR 136   // mod 32 == 8
#define PS_STR 68    // mod 32 == 4

// GEMM tiles
#define BM 128
#define BN 128
#define BK 32
#define XS_STR 36    // mod 32 == 4

__device__ float g_q[MAXS * DIM];
__device__ float g_k[MAXS * DIM];
__device__ float g_v[MAXS * DIM];
__device__ float g_o[MAXS * DIM];

__device__ __forceinline__ uint32_t f2tf32(float x) {
    uint32_t u;
    asm("cvt.rna.tf32.f32 %0, %1;" : "=r"(u) : "f"(x));
    return u;
}

// D += A*B  (m16n8k8, tf32 inputs as b32 regs, f32 accum)
__device__ __forceinline__ void mma8(float* d, const uint32_t* a, const uint32_t* b) {
    asm volatile(
        "mma.sync.aligned.m16n8k8.row.col.f32.tf32.tf32.f32 "
        "{%0,%1,%2,%3}, {%4,%5,%6,%7}, {%8,%9}, {%0,%1,%2,%3};"
        : "+f"(d[0]), "+f"(d[1]), "+f"(d[2]), "+f"(d[3])
        : "r"(a[0]), "r"(a[1]), "r"(a[2]), "r"(a[3]), "r"(b[0]), "r"(b[1]));
}

// ---------------------------------------------------------------------------
// tf32 mma.sync GEMM: Y[m][n] = sum_k X[m][k]*W[n][k] + bias[n]
// 128x128 CTA, 256 threads, warp tile 32(m) x 64(n).
// blockIdx.z picks (W,B,Y) set (fused QKV).
// ---------------------------------------------------------------------------
__global__ __launch_bounds__(256, 2) void gemm_mma(
    const float* __restrict__ X,
    const float* __restrict__ W0, const float* __restrict__ B0, float* __restrict__ Y0,
    const float* __restrict__ W1, const float* __restrict__ B1, float* __restrict__ Y1,
    const float* __restrict__ W2, const float* __restrict__ B2, float* __restrict__ Y2,
    int M)
{
    __shared__ uint32_t Xs[BM][XS_STR];
    __shared__ uint32_t Ws[BN][XS_STR];

    const float* W; const float* Bi; float* Y;
    if (blockIdx.z == 0)      { W = W0; Bi = B0; Y = Y0; }
    else if (blockIdx.z == 1) { W = W1; Bi = B1; Y = Y1; }
    else                      { W = W2; Bi = B2; Y = Y2; }

    const int t   = threadIdx.x;
    const int l   = t & 31;
    const int wid = t >> 5;
    const int wm  = (wid & 3) * 32;   // warp m offset
    const int wn  = (wid >> 2) * 64;  // warp n offset
    const int g   = l >> 2;           // groupID
    const int tg  = l & 3;            // thread in group
    const int m0  = blockIdx.x * BM;
    const int n0  = blockIdx.y * BN;

    const int lr = t >> 3;            // 0..31 load row
    const int ls = (t & 7) * 4;       // load col (floats)

    float acc[2][8][4];
#pragma unroll
    for (int i = 0; i < 2; i++)
#pragma unroll
        for (int j = 0; j < 8; j++)
#pragma unroll
            for (int c = 0; c < 4; c++) acc[i][j][c] = 0.0f;

    for (int c = 0; c < DIM / BK; c++) {
        __syncthreads();
        // stage 128x32 of X and W (4 rows-per-iter x 32 iters over 256 thr)
#pragma unroll
        for (int it = 0; it < 4; it++) {
            const int r = lr + it * 32;
            float4 xv = make_float4(0.f, 0.f, 0.f, 0.f);
            if (m0 + r < M) xv = *(const float4*)&X[(size_t)(m0 + r) * DIM + c * BK + ls];
            Xs[r][ls + 0] = f2tf32(xv.x); Xs[r][ls + 1] = f2tf32(xv.y);
            Xs[r][ls + 2] = f2tf32(xv.z); Xs[r][ls + 3] = f2tf32(xv.w);
            float4 wv = *(const float4*)&W[(size_t)(n0 + r) * DIM + c * BK + ls];
            Ws[r][ls + 0] = f2tf32(wv.x); Ws[r][ls + 1] = f2tf32(wv.y);
            Ws[r][ls + 2] = f2tf32(wv.z); Ws[r][ls + 3] = f2tf32(wv.w);
        }
        __syncthreads();

#pragma unroll
        for (int ks = 0; ks < 4; ks++) {
            const int k = ks * 8;
            uint32_t afr[2][4];
#pragma unroll
            for (int mt = 0; mt < 2; mt++) {
                const int r = wm + mt * 16 + g;
                afr[mt][0] = Xs[r][k + tg];
                afr[mt][1] = Xs[r + 8][k + tg];
                afr[mt][2] = Xs[r][k + 4 + tg];
                afr[mt][3] = Xs[r + 8][k + 4 + tg];
            }
#pragma unroll
            for (int nt = 0; nt < 8; nt++) {
                uint32_t bfr[2];
                const int n = wn + nt * 8 + g;
                bfr[0] = Ws[n][k + tg];
                bfr[1] = Ws[n][k + 4 + tg];
                mma8(acc[0][nt], afr[0], bfr);
                mma8(acc[1][nt], afr[1], bfr);
            }
        }
    }

    // epilogue: c0/c1 -> (row, 2tg), (row, 2tg+1); c2/c3 -> row+8
#pragma unroll
    for (int mt = 0; mt < 2; mt++) {
        const int r0 = m0 + wm + mt * 16 + g;
#pragma unroll
        for (int nt = 0; nt < 8; nt++) {
            const int cc = n0 + wn + nt * 8 + 2 * tg;
            const float b0 = Bi[cc], b1 = Bi[cc + 1];
            if (r0 < M) {
                float2 v = make_float2(acc[mt][nt][0] + b0, acc[mt][nt][1] + b1);
                *(float2*)&Y[(size_t)r0 * DIM + cc] = v;
            }
            if (r0 + 8 < M) {
                float2 v = make_float2(acc[mt][nt][2] + b0, acc[mt][nt][3] + b1);
                *(float2*)&Y[(size_t)(r0 + 8) * DIM + cc] = v;
            }
        }
    }
}

// ---------------------------------------------------------------------------
// RMSNorm + 3D causal RoPE (unchanged from R1)
// ---------------------------------------------------------------------------
__global__ __launch_bounds__(256) void rmsnorm_rope(
    float* __restrict__ q, float* __restrict__ k,
    const float* __restrict__ gq, const float* __restrict__ gk,
    const float* __restrict__ freqs,
    const int* __restrict__ grid_sizes,
    const int* __restrict__ cur_start_p, int S)
{
    const int s = blockIdx.x;
    const int which = blockIdx.y;
    float* row = (which ? k : q) + (size_t)s * DIM;
    const float* g = which ? gk : gq;

    __shared__ float red[8];
    __shared__ float cs[64], sn[64];
    const int t = threadIdx.x;

    float vals[6];
    float ss = 0.0f;
#pragma unroll
    for (int i = 0; i < 6; i++) {
        vals[i] = row[t + i * 256];
        ss += vals[i] * vals[i];
    }
#pragma unroll
    for (int o = 16; o; o >>= 1) ss += __shfl_xor_sync(0xffffffffu, ss, o);
    if ((t & 31) == 0) red[t >> 5] = ss;
    __syncthreads();
    if (t < 8) {
        float v = red[t];
#pragma unroll
        for (int o = 4; o; o >>= 1) v += __shfl_xor_sync(0xffu, v, o);
        if (t == 0) red[0] = v;
    }

    const int Hh = grid_sizes[1];
    const int Ww = grid_sizes[2];
    const int FHW = grid_sizes[0] * Hh * Ww;
    const bool rot = (s < FHW);

    if (rot && t < 64) {
        const int cur = cur_start_p[0];
        const int fs = Hh * Ww;
        const int sf = cur / fs;
        const int f = s / fs;
        const int rem = s - f * fs;
        const int h = rem / Ww;
        const int w = rem - h * Ww;
        int idx;
        if (t < 22)       idx = sf + f;
        else if (t < 43)  idx = h;
        else              idx = w;
        const float ang = freqs[idx * 64 + t];
        cs[t] = cosf(ang);
        sn[t] = sinf(ang);
    }
    __syncthreads();

    const float scale = rsqrtf(red[0] * (1.0f / DIM) + 1e-6f);

    if (rot) {
#pragma unroll
        for (int r = 0; r < 3; r++) {
            const int p = t + r * 256;
            const int j = p & 63;
            const int e0 = 2 * p, e1 = 2 * p + 1;
            const float a = row[e0] * scale * g[e0];
            const float b = row[e1] * scale * g[e1];
            const float c = cs[j], s_ = sn[j];
            row[e0] = a * c - b * s_;
            row[e1] = a * s_ + b * c;
        }
    } else {
#pragma unroll
        for (int i = 0; i < 6; i++) {
            const int e = t + i * 256;
            row[e] = vals[i] * scale * g[e];
        }
    }
}

// ---------------------------------------------------------------------------
// Flash attention on tf32 mma.sync.  4 warps; warp w owns q rows [16w,16w+16).
// grid = (ceil(S/64), NH), 128 threads.
// ---------------------------------------------------------------------------
__global__ __launch_bounds__(128, 2) void attention(
    const float* __restrict__ q,
    const float* __restrict__ knew, const float* __restrict__ vnew,
    const float* __restrict__ kcache, const float* __restrict__ vcache,
    float* __restrict__ o,
    const int* __restrict__ cur_start_p, int S)
{
    extern __shared__ uint32_t sm[];
    uint32_t* Ks = sm;                                  // [AKT][KS_STR]
    uint32_t* Vs = sm + AKT * KS_STR;                   // [AKT][VS_STR]
    uint32_t* Ps = sm + AKT * KS_STR + AKT * VS_STR;    // [AMT][PS_STR]

    const int head = blockIdx.y;
    const int q0 = blockIdx.x * AMT;
    const int t = threadIdx.x;
    const int l = t & 31;
    const int wid = t >> 5;
    const int g = l >> 2;
    const int tg = l & 3;

    const int cur = cur_start_p[0];
    const int cur_end = cur + S;
    int win_start = cur_end - MAX_ATTN_W;
    if (win_start < 0) win_start = 0;
    const int Lw = cur_end - win_start;

    // preload Q A-fragments for this warp's 16 rows (16 ksteps x 4 regs)
    const int row0 = q0 + wid * 16 + g;
    const size_t qb0 = (size_t)row0 * DIM + head * HD;
    const size_t qb1 = (size_t)(row0 + 8) * DIM + head * HD;
    const bool r0ok = row0 < S, r1ok = (row0 + 8) < S;
    uint32_t qa[16][4];
#pragma unroll
    for (int ks = 0; ks < 16; ks++) {
        const int k = ks * 8 + tg;
        qa[ks][0] = r0ok ? f2tf32(q[qb0 + k])     : 0u;
        qa[ks][1] = r1ok ? f2tf32(q[qb1 + k])     : 0u;
        qa[ks][2] = r0ok ? f2tf32(q[qb0 + k + 4]) : 0u;
        qa[ks][3] = r1ok ? f2tf32(q[qb1 + k + 4]) : 0u;
    }

    float o_acc[16][4];
#pragma unroll
    for (int nt = 0; nt < 16; nt++)
#pragma unroll
        for (int c = 0; c < 4; c++) o_acc[nt][c] = 0.0f;
    float mA = -1e30f, mB = -1e30f, lA = 0.0f, lB = 0.0f;

    const int ntiles = (Lw + AKT - 1) / AKT;
    const float sc = 0.08838834764831845f;

    for (int tile = 0; tile < ntiles; tile++) {
        const int kbase = win_start + tile * AKT;
        __syncthreads();
        // stage K,V (64 tokens x 128 dims), tf32-converted
        for (int i = t; i < AKT * 32; i += 128) {
            const int r = i >> 5, c4 = (i & 31) * 4;
            const int tok = kbase + r;
            float4 kv = make_float4(0.f, 0.f, 0.f, 0.f);
            float4 vv = make_float4(0.f, 0.f, 0.f, 0.f);
            if (tok < cur_end) {
                if (tok < cur) {
                    const size_t off = ((size_t)tok * NH + head) * HD + c4;
                    kv = *(const float4*)&kcache[off];
                    vv = *(const float4*)&vcache[off];
                } else {
                    const size_t off = (size_t)(tok - cur) * DIM + head * HD + c4;
                    kv = *(const float4*)&knew[off];
                    vv = *(const float4*)&vnew[off];
                }
            }
            uint32_t* kr = Ks + r * KS_STR + c4;
            kr[0] = f2tf32(kv.x); kr[1] = f2tf32(kv.y); kr[2] = f2tf32(kv.z); kr[3] = f2tf32(kv.w);
            uint32_t* vr = Vs + r * VS_STR + c4;
            vr[0] = f2tf32(vv.x); vr[1] = f2tf32(vv.y); vr[2] = f2tf32(vv.z); vr[3] = f2tf32(vv.w);
        }
        __syncthreads();

        // S = Q K^T  (8 n-tiles of 8 keys)
        float s_acc[8][4];
#pragma unroll
        for (int nt = 0; nt < 8; nt++)
#pragma unroll
            for (int c = 0; c < 4; c++) s_acc[nt][c] = 0.0f;

#pragma unroll 4
        for (int ks = 0; ks < 16; ks++) {
            const int k = ks * 8 + tg;
#pragma unroll
            for (int nt = 0; nt < 8; nt++) {
                uint32_t bfr[2];
                const uint32_t* kp = Ks + (nt * 8 + g) * KS_STR + k;
                bfr[0] = kp[0];
                bfr[1] = kp[4];
                mma8(s_acc[nt], qa[ks], bfr);
            }
        }

        // scale + mask
#pragma unroll
        for (int nt = 0; nt < 8; nt++) {
            const int key0 = kbase + nt * 8 + 2 * tg;
            const bool ok0 = key0 < cur_end, ok1 = (key0 + 1) < cur_end;
            s_acc[nt][0] = ok0 ? s_acc[nt][0] * sc : -1e30f;
            s_acc[nt][1] = ok1 ? s_acc[nt][1] * sc : -1e30f;
            s_acc[nt][2] = ok0 ? s_acc[nt][2] * sc : -1e30f;
            s_acc[nt][3] = ok1 ? s_acc[nt][3] * sc : -1e30f;
        }

        // online softmax (rows A: c0/c1, rows B: c2/c3); 4 lanes share a row
        float rmA = -1e30f, rmB = -1e30f;
#pragma unroll
        for (int nt = 0; nt < 8; nt++) {
            rmA = fmaxf(rmA, fmaxf(s_acc[nt][0], s_acc[nt][1]));
            rmB = fmaxf(rmB, fmaxf(s_acc[nt][2], s_acc[nt][3]));
        }
        rmA = fmaxf(rmA, __shfl_xor_sync(0xffffffffu, rmA, 1));
        rmA = fmaxf(rmA, __shfl_xor_sync(0xffffffffu, rmA, 2));
        rmB = fmaxf(rmB, __shfl_xor_sync(0xffffffffu, rmB, 1));
        rmB = fmaxf(rmB, __shfl_xor_sync(0xffffffffu, rmB, 2));
        const float nmA = fmaxf(mA, rmA), nmB = fmaxf(mB, rmB);
        const float aA = __expf(mA - nmA), aB = __expf(mB - nmB);
        mA = nmA; mB = nmB;

        float sumA = 0.0f, sumB = 0.0f;
        uint32_t* pr0 = Ps + (wid * 16 + g) * PS_STR + 2 * tg;
        uint32_t* pr1 = pr0 + 8 * PS_STR;
#pragma unroll
        for (int nt = 0; nt < 8; nt++) {
            const float p0 = __expf(s_acc[nt][0] - nmA);
            const float p1 = __expf(s_acc[nt][1] - nmA);
            const float p2 = __expf(s_acc[nt][2] - nmB);
            const float p3 = __expf(s_acc[nt][3] - nmB);
            sumA += p0 + p1; sumB += p2 + p3;
            pr0[nt * 8 + 0] = f2tf32(p0); pr0[nt * 8 + 1] = f2tf32(p1);
            pr1[nt * 8 + 0] = f2tf32(p2); pr1[nt * 8 + 1] = f2tf32(p3);
        }
        sumA += __shfl_xor_sync(0xffffffffu, sumA, 1);
        sumA += __shfl_xor_sync(0xffffffffu, sumA, 2);
        sumB += __shfl_xor_sync(0xffffffffu, sumB, 1);
        sumB += __shfl_xor_sync(0xffffffffu, sumB, 2);
        lA = lA * aA + sumA;
        lB = lB * aB + sumB;

#pragma unroll
        for (int nt = 0; nt < 16; nt++) {
            o_acc[nt][0] *= aA; o_acc[nt][1] *= aA;
            o_acc[nt][2] *= aB; o_acc[nt][3] *= aB;
        }
        __syncwarp();

        // O += P V   (A = P rows of this warp, B = V)
#pragma unroll 2
        for (int ks = 0; ks < 8; ks++) {
            const int k = ks * 8 + tg;
            uint32_t afr[4];
            const uint32_t* pp = Ps + (wid * 16 + g) * PS_STR + k;
            afr[0] = pp[0];
            afr[1] = pp[8 * PS_STR];
            afr[2] = pp[4];
            afr[3] = pp[8 * PS_STR + 4];
#pragma unroll
            for (int nt = 0; nt < 16; nt++) {
                uint32_t bfr[2];
                const uint32_t* vp = Vs + k * VS_STR + nt * 8 + g;
                bfr[0] = vp[0];
                bfr[1] = vp[4 * VS_STR];
                mma8(o_acc[nt], afr, bfr);
            }
        }
        __syncwarp();
    }

    // write normalized output
    const float iA = 1.0f / lA, iB = 1.0f / lB;
#pragma unroll
    for (int nt = 0; nt < 16; nt++) {
        const int cc = head * HD + nt * 8 + 2 * tg;
        if (r0ok) {
            float2 v = make_float2(o_acc[nt][0] * iA, o_acc[nt][1] * iA);
            *(float2*)&o[(size_t)row0 * DIM + cc] = v;
        }
        if (r1ok) {
            float2 v = make_float2(o_acc[nt][2] * iB, o_acc[nt][3] * iB);
            *(float2*)&o[(size_t)(row0 + 8) * DIM + cc] = v;
        }
    }
}

// ---------------------------------------------------------------------------
extern "C" void kernel_launch(void* const* d_in, const int* in_sizes, int n_in,
                              void* d_out, int out_size)
{
    const float* x      = (const float*)d_in[0];
    const float* freqs  = (const float*)d_in[1];
    const float* wq     = (const float*)d_in[2];
    const float* bq     = (const float*)d_in[3];
    const float* wk     = (const float*)d_in[4];
    const float* bk     = (const float*)d_in[5];
    const float* wv     = (const float*)d_in[6];
    const float* bv     = (const float*)d_in[7];
    const float* wo     = (const float*)d_in[8];
    const float* bo     = (const float*)d_in[9];
    const float* gq     = (const float*)d_in[10];
    const float* gk     = (const float*)d_in[11];
    const float* kcache = (const float*)d_in[12];
    const float* vcache = (const float*)d_in[13];
    const int* grid_sizes = (const int*)d_in[14];
    const int* cur_start  = (const int*)d_in[16];

    const int S = in_sizes[0] / DIM;

    float *q, *k, *v, *o;
    cudaGetSymbolAddress((void**)&q, g_q);
    cudaGetSymbolAddress((void**)&k, g_k);
    cudaGetSymbolAddress((void**)&v, g_v);
    cudaGetSymbolAddress((void**)&o, g_o);

    // fused QKV projections
    gemm_mma<<<dim3((S + BM - 1) / BM, DIM / BN, 3), 256>>>(
        x, wq, bq, q, wk, bk, k, wv, bv, v, S);

    rmsnorm_rope<<<dim3(S, 2), 256>>>(q, k, gq, gk, freqs, grid_sizes, cur_start, S);

    const int asmem = (AKT * KS_STR + AKT * VS_STR + AMT * PS_STR) * 4;  // 86016
    cudaFuncSetAttribute(attention, cudaFuncAttributeMaxDynamicSharedMemorySize, asmem);
    attention<<<dim3((S + AMT - 1) / AMT, NH), 128, asmem>>>(
        q, k, v, kcache, vcache, o, cur_start, S);

    // output projection
    gemm_mma<<<dim3((S + BM - 1) / BM, DIM / BN, 1), 256>>>(
        o, wo, bo, (float*)d_out, wo, bo, (float*)d_out, wo, bo, (float*)d_out, S);
}

// round 5
// speedup vs baseline: 2.5856x; 1.3091x over previous
#include <cuda_runtime.h>
#include <cuda_fp16.h>
#include <math.h>
#include <stdint.h>

#define DIM 1536
#define NH 12
#define HD 128
#define MAXS 2048
#define MAX_ATTN_W 32760
#define GSTR 40          // GEMM smem row stride (halfs)
#define ASTR 136         // attention smem row stride (halfs)

__device__ float  g_q[MAXS * DIM];
__device__ float  g_k[MAXS * DIM];
__device__ float  g_v[MAXS * DIM];
__device__ __half g_x16[MAXS * DIM];
__device__ __half g_o16[MAXS * DIM];
__device__ __half g_wq16[DIM * DIM];
__device__ __half g_wk16[DIM * DIM];
__device__ __half g_wv16[DIM * DIM];
__device__ __half g_wo16[DIM * DIM];

// ---------------------------------------------------------------------------
__device__ __forceinline__ uint32_t smem_u32(const void* p) {
    uint32_t a;
    asm("{ .reg .u64 t; cvta.to.shared.u64 t, %1; cvt.u32.u64 %0, t; }" : "=r"(a) : "l"(p));
    return a;
}
__device__ __forceinline__ uint32_t pkh(float a, float b) {
    __half2 h = __floats2half2_rn(a, b);
    return *(uint32_t*)&h;
}
__device__ __forceinline__ void mma16(float* d, const uint32_t* a, uint32_t b0, uint32_t b1) {
    asm volatile(
        "mma.sync.aligned.m16n8k16.row.col.f32.f16.f16.f32 "
        "{%0,%1,%2,%3},{%4,%5,%6,%7},{%8,%9},{%0,%1,%2,%3};"
        : "+f"(d[0]), "+f"(d[1]), "+f"(d[2]), "+f"(d[3])
        : "r"(a[0]), "r"(a[1]), "r"(a[2]), "r"(a[3]), "r"(b0), "r"(b1));
}
__device__ __forceinline__ void ldsm4(uint32_t& r0, uint32_t& r1, uint32_t& r2, uint32_t& r3,
                                      uint32_t a) {
    asm volatile("ldmatrix.sync.aligned.m8n8.x4.shared.b16 {%0,%1,%2,%3}, [%4];"
                 : "=r"(r0), "=r"(r1), "=r"(r2), "=r"(r3) : "r"(a));
}
__device__ __forceinline__ void ldsm4t(uint32_t& r0, uint32_t& r1, uint32_t& r2, uint32_t& r3,
                                       uint32_t a) {
    asm volatile("ldmatrix.sync.aligned.m8n8.x4.trans.shared.b16 {%0,%1,%2,%3}, [%4];"
                 : "=r"(r0), "=r"(r1), "=r"(r2), "=r"(r3) : "r"(a));
}
__device__ __forceinline__ void cp16(uint32_t dst, const void* src) {
    asm volatile("cp.async.cg.shared.global [%0], [%1], 16;" :: "r"(dst), "l"(src));
}
__device__ __forceinline__ void cp16z(uint32_t dst, const void* src, int sz) {
    asm volatile("cp.async.cg.shared.global [%0], [%1], 16, %2;" :: "r"(dst), "l"(src), "r"(sz));
}
#define CP_COMMIT() asm volatile("cp.async.commit_group;" ::: "memory")
#define CP_WAIT(n)  asm volatile("cp.async.wait_group %0;" :: "n"(n) : "memory")

// ---------------------------------------------------------------------------
__global__ void cvt16(const float* __restrict__ in, __half* __restrict__ out, int n4) {
    int i = blockIdx.x * blockDim.x + threadIdx.x;
    if (i < n4) {
        float4 v = ((const float4*)in)[i];
        ((__half2*)out)[2 * i]     = __floats2half2_rn(v.x, v.y);
        ((__half2*)out)[2 * i + 1] = __floats2half2_rn(v.z, v.w);
    }
}

// ---------------------------------------------------------------------------
// fp16 GEMM: Y[m][n] = sum_k A[m][k]*W[n][k] + bias[n].  128x128 tile, BK=32,
// cp.async double-buffered, 256 threads, warp 32(m)x64(n).
// ---------------------------------------------------------------------------
__device__ __forceinline__ void gemm_stage(
    const __half* __restrict__ A, const __half* __restrict__ W,
    uint32_t sa, uint32_t sw, int kc, int m0, int n0, int M, int t)
{
#pragma unroll
    for (int i = 0; i < 2; i++) {
        const int id = t + i * 256;
        const int row = id >> 2, slot = id & 3;
        const int ar = m0 + row;
        const __half* asrc = A + (size_t)(ar < M ? ar : 0) * DIM + kc * 32 + slot * 8;
        cp16z(sa + (uint32_t)(row * GSTR + slot * 8) * 2, asrc, ar < M ? 16 : 0);
        cp16(sw + (uint32_t)(row * GSTR + slot * 8) * 2,
             W + (size_t)(n0 + row) * DIM + kc * 32 + slot * 8);
    }
    CP_COMMIT();
}

__global__ __launch_bounds__(256, 2) void gemm_h16(
    const __half* __restrict__ A,
    const __half* __restrict__ W0, const float* __restrict__ B0, float* __restrict__ Y0,
    const __half* __restrict__ W1, const float* __restrict__ B1, float* __restrict__ Y1,
    const __half* __restrict__ W2, const float* __restrict__ B2, float* __restrict__ Y2,
    int M)
{
    __shared__ __half SA[2][128 * GSTR];
    __shared__ __half SW[2][128 * GSTR];

    const __half* W; const float* Bi; float* Y;
    if (blockIdx.z == 0)      { W = W0; Bi = B0; Y = Y0; }
    else if (blockIdx.z == 1) { W = W1; Bi = B1; Y = Y1; }
    else                      { W = W2; Bi = B2; Y = Y2; }

    const int t = threadIdx.x, l = t & 31, wid = t >> 5;
    const int wm = (wid & 3) * 32, wn = (wid >> 2) * 64;
    const int g = l >> 2, tg = l & 3;
    const int m0 = blockIdx.x * 128, n0 = blockIdx.y * 128;

    const uint32_t saw[2] = { smem_u32(SA[0]), smem_u32(SA[1]) };
    const uint32_t sww[2] = { smem_u32(SW[0]), smem_u32(SW[1]) };

    const int a_row = (l & 7) + 8 * ((l >> 3) & 1);
    const int a_half = 8 * ((l >> 4) & 1);
    const int b_row = (l & 7) + 8 * ((l >> 4) & 1);
    const int b_half = 8 * ((l >> 3) & 1);

    float acc[2][8][4];
#pragma unroll
    for (int i = 0; i < 2; i++)
#pragma unroll
        for (int j = 0; j < 8; j++)
#pragma unroll
            for (int c = 0; c < 4; c++) acc[i][j][c] = 0.0f;

    gemm_stage(A, W, saw[0], sww[0], 0, m0, n0, M, t);

    for (int kc = 0; kc < DIM / 32; kc++) {
        const int b = kc & 1;
        if (kc + 1 < DIM / 32) {
            gemm_stage(A, W, saw[1 - b], sww[1 - b], kc + 1, m0, n0, M, t);
            CP_WAIT(1);
        } else {
            CP_WAIT(0);
        }
        __syncthreads();

        const uint32_t ab = saw[b], wb = sww[b];
#pragma unroll
        for (int ks = 0; ks < 2; ks++) {
            uint32_t af[2][4];
            ldsm4(af[0][0], af[0][1], af[0][2], af[0][3],
                  ab + (uint32_t)((wm + a_row) * GSTR + 16 * ks + a_half) * 2);
            ldsm4(af[1][0], af[1][1], af[1][2], af[1][3],
                  ab + (uint32_t)((wm + 16 + a_row) * GSTR + 16 * ks + a_half) * 2);
#pragma unroll
            for (int j = 0; j < 4; j++) {
                uint32_t b0, b1, b2, b3;
                ldsm4(b0, b1, b2, b3,
                      wb + (uint32_t)((wn + 16 * j + b_row) * GSTR + 16 * ks + b_half) * 2);
                mma16(acc[0][2 * j],     af[0], b0, b1);
                mma16(acc[0][2 * j + 1], af[0], b2, b3);
                mma16(acc[1][2 * j],     af[1], b0, b1);
                mma16(acc[1][2 * j + 1], af[1], b2, b3);
            }
        }
        __syncthreads();
    }

#pragma unroll
    for (int mt = 0; mt < 2; mt++) {
        const int r0 = m0 + wm + mt * 16 + g;
#pragma unroll
        for (int nt = 0; nt < 8; nt++) {
            const int cc = n0 + wn + nt * 8 + 2 * tg;
            const float b0 = Bi[cc], b1 = Bi[cc + 1];
            if (r0 < M) {
                float2 v = make_float2(acc[mt][nt][0] + b0, acc[mt][nt][1] + b1);
                *(float2*)&Y[(size_t)r0 * DIM + cc] = v;
            }
            if (r0 + 8 < M) {
                float2 v = make_float2(acc[mt][nt][2] + b0, acc[mt][nt][3] + b1);
                *(float2*)&Y[(size_t)(r0 + 8) * DIM + cc] = v;
            }
        }
    }
}

// ---------------------------------------------------------------------------
// RMSNorm + 3D causal RoPE (unchanged; fp32 in place)
// ---------------------------------------------------------------------------
__global__ __launch_bounds__(256) void rmsnorm_rope(
    float* __restrict__ q, float* __restrict__ k,
    const float* __restrict__ gq, const float* __restrict__ gk,
    const float* __restrict__ freqs,
    const int* __restrict__ grid_sizes,
    const int* __restrict__ cur_start_p, int S)
{
    const int s = blockIdx.x;
    const int which = blockIdx.y;
    float* row = (which ? k : q) + (size_t)s * DIM;
    const float* g = which ? gk : gq;

    __shared__ float red[8];
    __shared__ float cs[64], sn[64];
    const int t = threadIdx.x;

    float vals[6];
    float ss = 0.0f;
#pragma unroll
    for (int i = 0; i < 6; i++) {
        vals[i] = row[t + i * 256];
        ss += vals[i] * vals[i];
    }
#pragma unroll
    for (int o = 16; o; o >>= 1) ss += __shfl_xor_sync(0xffffffffu, ss, o);
    if ((t & 31) == 0) red[t >> 5] = ss;
    __syncthreads();
    if (t < 8) {
        float v = red[t];
#pragma unroll
        for (int o = 4; o; o >>= 1) v += __shfl_xor_sync(0xffu, v, o);
        if (t == 0) red[0] = v;
    }

    const int Hh = grid_sizes[1];
    const int Ww = grid_sizes[2];
    const int FHW = grid_sizes[0] * Hh * Ww;
    const bool rot = (s < FHW);

    if (rot && t < 64) {
        const int cur = cur_start_p[0];
        const int fs = Hh * Ww;
        const int sf = cur / fs;
        const int f = s / fs;
        const int rem = s - f * fs;
        const int h = rem / Ww;
        const int w = rem - h * Ww;
        int idx;
        if (t < 22)       idx = sf + f;
        else if (t < 43)  idx = h;
        else              idx = w;
        const float ang = freqs[idx * 64 + t];
        cs[t] = cosf(ang);
        sn[t] = sinf(ang);
    }
    __syncthreads();

    const float scale = rsqrtf(red[0] * (1.0f / DIM) + 1e-6f);

    if (rot) {
#pragma unroll
        for (int r = 0; r < 3; r++) {
            const int p = t + r * 256;
            const int j = p & 63;
            const int e0 = 2 * p, e1 = 2 * p + 1;
            const float a = row[e0] * scale * g[e0];
            const float b = row[e1] * scale * g[e1];
            const float c = cs[j], s_ = sn[j];
            row[e0] = a * c - b * s_;
            row[e1] = a * s_ + b * c;
        }
    } else {
#pragma unroll
        for (int i = 0; i < 6; i++) {
            const int e = t + i * 256;
            row[e] = vals[i] * scale * g[e];
        }
    }
}

// ---------------------------------------------------------------------------
// fp16 flash attention. 4 warps x 16 q-rows, 64-key tiles, ldmatrix frags,
// P kept in registers (C->A fragment identity). Writes fp16 output.
// ---------------------------------------------------------------------------
__global__ __launch_bounds__(128, 2) void attn_h16(
    const float* __restrict__ q,
    const float* __restrict__ knew, const float* __restrict__ vnew,
    const float* __restrict__ kcache, const float* __restrict__ vcache,
    __half* __restrict__ o16,
    const int* __restrict__ cur_start_p, int S)
{
    __shared__ __half Ks[64 * ASTR];
    __shared__ __half Vs[64 * ASTR];

    const int hh = blockIdx.y;
    const int q0 = blockIdx.x * 64;
    const int t = threadIdx.x, l = t & 31, wid = t >> 5;
    const int g = l >> 2, tg = l & 3;

    const int cur = cur_start_p[0];
    const int cur_end = cur + S;
    int ws = cur_end - MAX_ATTN_W; if (ws < 0) ws = 0;
    const int Lw = cur_end - ws;
    const int ntiles = (Lw + 63) >> 6;

    const uint32_t ksb = smem_u32(Ks), vsb = smem_u32(Vs);
    const int k_row = (l & 7) + ((l >> 4) & 1) * 8;
    const int k_half = ((l >> 3) & 1) * 8;
    const int v_row = (l & 7) + ((l >> 3) & 1) * 8;
    const int v_dim = ((l >> 4) & 1) * 8;

    // Q A-fragments (fp32 -> fp16 once)
    const int row0 = q0 + wid * 16 + g;
    const bool r0ok = row0 < S, r1ok = (row0 + 8) < S;
    uint32_t qa[8][4];
    {
        const float2* qp0 = (const float2*)(q + (size_t)(r0ok ? row0 : 0) * DIM + hh * HD);
        const float2* qp1 = (const float2*)(q + (size_t)(r1ok ? row0 + 8 : 0) * DIM + hh * HD);
#pragma unroll
        for (int ks = 0; ks < 8; ks++) {
            float2 x0 = qp0[8 * ks + tg],     x1 = qp1[8 * ks + tg];
            float2 x2 = qp0[8 * ks + tg + 4], x3 = qp1[8 * ks + tg + 4];
            qa[ks][0] = r0ok ? pkh(x0.x, x0.y) : 0u;
            qa[ks][1] = r1ok ? pkh(x1.x, x1.y) : 0u;
            qa[ks][2] = r0ok ? pkh(x2.x, x2.y) : 0u;
            qa[ks][3] = r1ok ? pkh(x3.x, x3.y) : 0u;
        }
    }

    float o_acc[16][4];
#pragma unroll
    for (int nt = 0; nt < 16; nt++)
#pragma unroll
        for (int c = 0; c < 4; c++) o_acc[nt][c] = 0.0f;
    float mA = -1e30f, mB = -1e30f, lA = 0.0f, lB = 0.0f;
    const float sc = 0.08838834764831845f;

    for (int tile = 0; tile < ntiles; tile++) {
        const int kbase = ws + tile * 64;
        __syncthreads();
        // stage K,V fp32 -> fp16
#pragma unroll
        for (int i2 = 0; i2 < 16; i2++) {
            const int i = t + i2 * 128;
            const int r = i >> 5, c4 = (i & 31) * 4;
            const int tok = kbase + r;
            float4 kv = make_float4(0.f, 0.f, 0.f, 0.f);
            float4 vv = make_float4(0.f, 0.f, 0.f, 0.f);
            if (tok < cur_end) {
                if (tok < cur) {
                    const size_t off = ((size_t)tok * NH + hh) * HD + c4;
                    kv = *(const float4*)&kcache[off];
                    vv = *(const float4*)&vcache[off];
                } else {
                    const size_t off = (size_t)(tok - cur) * DIM + hh * HD + c4;
                    kv = *(const float4*)&knew[off];
                    vv = *(const float4*)&vnew[off];
                }
            }
            uint2 kp; kp.x = pkh(kv.x, kv.y); kp.y = pkh(kv.z, kv.w);
            *(uint2*)&Ks[r * ASTR + c4] = kp;
            uint2 vp; vp.x = pkh(vv.x, vv.y); vp.y = pkh(vv.z, vv.w);
            *(uint2*)&Vs[r * ASTR + c4] = vp;
        }
        __syncthreads();

        // S = Q K^T
        float s_acc[8][4];
#pragma unroll
        for (int nt = 0; nt < 8; nt++)
#pragma unroll
            for (int c = 0; c < 4; c++) s_acc[nt][c] = 0.0f;
#pragma unroll
        for (int ks = 0; ks < 8; ks++) {
#pragma unroll
            for (int j = 0; j < 4; j++) {
                uint32_t b0, b1, b2, b3;
                ldsm4(b0, b1, b2, b3,
                      ksb + (uint32_t)((16 * j + k_row) * ASTR + 16 * ks + k_half) * 2);
                mma16(s_acc[2 * j],     qa[ks], b0, b1);
                mma16(s_acc[2 * j + 1], qa[ks], b2, b3);
            }
        }

        // scale + mask (window-relative columns)
        const int kb = tile * 64;
#pragma unroll
        for (int nt = 0; nt < 8; nt++) {
            const int key0 = kb + nt * 8 + 2 * tg;
            const bool ok0 = key0 < Lw, ok1 = (key0 + 1) < Lw;
            s_acc[nt][0] = ok0 ? s_acc[nt][0] * sc : -1e30f;
            s_acc[nt][1] = ok1 ? s_acc[nt][1] * sc : -1e30f;
            s_acc[nt][2] = ok0 ? s_acc[nt][2] * sc : -1e30f;
            s_acc[nt][3] = ok1 ? s_acc[nt][3] * sc : -1e30f;
        }

        // online softmax; rows: c0/c1 -> row g (A), c2/c3 -> row g+8 (B)
        float rmA = -1e30f, rmB = -1e30f;
#pragma unroll
        for (int nt = 0; nt < 8; nt++) {
            rmA = fmaxf(rmA, fmaxf(s_acc[nt][0], s_acc[nt][1]));
            rmB = fmaxf(rmB, fmaxf(s_acc[nt][2], s_acc[nt][3]));
        }
        rmA = fmaxf(rmA, __shfl_xor_sync(0xffffffffu, rmA, 1));
        rmA = fmaxf(rmA, __shfl_xor_sync(0xffffffffu, rmA, 2));
        rmB = fmaxf(rmB, __shfl_xor_sync(0xffffffffu, rmB, 1));
        rmB = fmaxf(rmB, __shfl_xor_sync(0xffffffffu, rmB, 2));
        const float nmA = fmaxf(mA, rmA), nmB = fmaxf(mB, rmB);
        const float aA = __expf(mA - nmA), aB = __expf(mB - nmB);
        mA = nmA; mB = nmB;

        float suA = 0.0f, suB = 0.0f;
#pragma unroll
        for (int nt = 0; nt < 8; nt++) {
            s_acc[nt][0] = __expf(s_acc[nt][0] - nmA);
            s_acc[nt][1] = __expf(s_acc[nt][1] - nmA);
            s_acc[nt][2] = __expf(s_acc[nt][2] - nmB);
            s_acc[nt][3] = __expf(s_acc[nt][3] - nmB);
            suA += s_acc[nt][0] + s_acc[nt][1];
            suB += s_acc[nt][2] + s_acc[nt][3];
        }
        suA += __shfl_xor_sync(0xffffffffu, suA, 1);
        suA += __shfl_xor_sync(0xffffffffu, suA, 2);
        suB += __shfl_xor_sync(0xffffffffu, suB, 1);
        suB += __shfl_xor_sync(0xffffffffu, suB, 2);
        lA = lA * aA + suA;
        lB = lB * aB + suB;

#pragma unroll
        for (int nt = 0; nt < 16; nt++) {
            o_acc[nt][0] *= aA; o_acc[nt][1] *= aA;
            o_acc[nt][2] *= aB; o_acc[nt][3] *= aB;
        }

        // O += P V   (A-fragments straight from registers)
#pragma unroll
        for (int ks = 0; ks < 4; ks++) {
            uint32_t ap[4];
            ap[0] = pkh(s_acc[2 * ks][0],     s_acc[2 * ks][1]);
            ap[1] = pkh(s_acc[2 * ks][2],     s_acc[2 * ks][3]);
            ap[2] = pkh(s_acc[2 * ks + 1][0], s_acc[2 * ks + 1][1]);
            ap[3] = pkh(s_acc[2 * ks + 1][2], s_acc[2 * ks + 1][3]);
#pragma unroll
            for (int j = 0; j < 8; j++) {
                uint32_t b0, b1, b2, b3;
                ldsm4t(b0, b1, b2, b3,
                       vsb + (uint32_t)((16 * ks + v_row) * ASTR + 16 * j + v_dim) * 2);
                mma16(o_acc[2 * j],     ap, b0, b1);
                mma16(o_acc[2 * j + 1], ap, b2, b3);
            }
        }
    }

    // write fp16 output
    const float iA = 1.0f / lA, iB = 1.0f / lB;
#pragma unroll
    for (int nt = 0; nt < 16; nt++) {
        const int cc = hh * HD + nt * 8 + 2 * tg;
        if (r0ok)
            *(uint32_t*)&o16[(size_t)row0 * DIM + cc] = pkh(o_acc[nt][0] * iA, o_acc[nt][1] * iA);
        if (r1ok)
            *(uint32_t*)&o16[(size_t)(row0 + 8) * DIM + cc] = pkh(o_acc[nt][2] * iB, o_acc[nt][3] * iB);
    }
}

// ---------------------------------------------------------------------------
extern "C" void kernel_launch(void* const* d_in, const int* in_sizes, int n_in,
                              void* d_out, int out_size)
{
    const float* x      = (const float*)d_in[0];
    const float* freqs  = (const float*)d_in[1];
    const float* wq     = (const float*)d_in[2];
    const float* bq     = (const float*)d_in[3];
    const float* wk     = (const float*)d_in[4];
    const float* bk     = (const float*)d_in[5];
    const float* wv     = (const float*)d_in[6];
    const float* bv     = (const float*)d_in[7];
    const float* wo     = (const float*)d_in[8];
    const float* bo     = (const float*)d_in[9];
    const float* gq     = (const float*)d_in[10];
    const float* gk     = (const float*)d_in[11];
    const float* kcache = (const float*)d_in[12];
    const float* vcache = (const float*)d_in[13];
    const int* grid_sizes = (const int*)d_in[14];
    const int* cur_start  = (const int*)d_in[16];

    const int S = in_sizes[0] / DIM;

    float *q, *k, *v;
    __half *x16, *o16, *wq16, *wk16, *wv16, *wo16;
    cudaGetSymbolAddress((void**)&q, g_q);
    cudaGetSymbolAddress((void**)&k, g_k);
    cudaGetSymbolAddress((void**)&v, g_v);
    cudaGetSymbolAddress((void**)&x16, g_x16);
    cudaGetSymbolAddress((void**)&o16, g_o16);
    cudaGetSymbolAddress((void**)&wq16, g_wq16);
    cudaGetSymbolAddress((void**)&wk16, g_wk16);
    cudaGetSymbolAddress((void**)&wv16, g_wv16);
    cudaGetSymbolAddress((void**)&wo16, g_wo16);

    const int wn4 = DIM * DIM / 4;
    const int xn4 = S * DIM / 4;
    cvt16<<<(xn4 + 255) / 256, 256>>>(x, x16, xn4);
    cvt16<<<(wn4 + 255) / 256, 256>>>(wq, wq16, wn4);
    cvt16<<<(wn4 + 255) / 256, 256>>>(wk, wk16, wn4);
    cvt16<<<(wn4 + 255) / 256, 256>>>(wv, wv16, wn4);
    cvt16<<<(wn4 + 255) / 256, 256>>>(wo, wo16, wn4);

    // fused QKV projections
    gemm_h16<<<dim3((S + 127) / 128, DIM / 128, 3), 256>>>(
        x16, wq16, bq, q, wk16, bk, k, wv16, bv, v, S);

    rmsnorm_rope<<<dim3(S, 2), 256>>>(q, k, gq, gk, freqs, grid_sizes, cur_start, S);

    attn_h16<<<dim3((S + 63) / 64, NH), 128>>>(
        q, k, v, kcache, vcache, o16, cur_start, S);

    // output projection
    gemm_h16<<<dim3((S + 127) / 128, DIM / 128, 1), 256>>>(
        o16, wo16, bo, (float*)d_out, wo16, bo, (float*)d_out, wo16, bo, (float*)d_out, S);
}

// round 6
// speedup vs baseline: 7.2769x; 2.8144x over previous
#include <cuda_runtime.h>
#include <cuda_fp16.h>
#include <math.h>
#include <stdint.h>

#define DIM 1536
#define NH 12
#define HD 128
#define MAXS 2048
#define MAX_ATTN_W 32760
#define LWMAX 8192       // max materialized window (tokens)
#define GSTR 40          // GEMM smem row stride (halfs)
#define ASTR 136         // attention smem row stride (halfs)
#define ABUF (64 * ASTR) // one K or V tile buffer (halfs)

__device__ float  g_q[MAXS * DIM];
__device__ float  g_k[MAXS * DIM];
__device__ float  g_v[MAXS * DIM];
__device__ __half g_x16[MAXS * DIM];
__device__ __half g_o16[MAXS * DIM];
__device__ __half g_wq16[DIM * DIM];
__device__ __half g_wk16[DIM * DIM];
__device__ __half g_wv16[DIM * DIM];
__device__ __half g_wo16[DIM * DIM];
__device__ __half g_ku[(size_t)NH * LWMAX * HD];
__device__ __half g_vu[(size_t)NH * LWMAX * HD];

// ---------------------------------------------------------------------------
__device__ __forceinline__ uint32_t smem_u32(const void* p) {
    uint32_t a;
    asm("{ .reg .u64 t; cvta.to.shared.u64 t, %1; cvt.u32.u64 %0, t; }" : "=r"(a) : "l"(p));
    return a;
}
__device__ __forceinline__ uint32_t pkh(float a, float b) {
    __half2 h = __floats2half2_rn(a, b);
    return *(uint32_t*)&h;
}
__device__ __forceinline__ void mma16(float* d, const uint32_t* a, uint32_t b0, uint32_t b1) {
    asm volatile(
        "mma.sync.aligned.m16n8k16.row.col.f32.f16.f16.f32 "
        "{%0,%1,%2,%3},{%4,%5,%6,%7},{%8,%9},{%0,%1,%2,%3};"
        : "+f"(d[0]), "+f"(d[1]), "+f"(d[2]), "+f"(d[3])
        : "r"(a[0]), "r"(a[1]), "r"(a[2]), "r"(a[3]), "r"(b0), "r"(b1));
}
__device__ __forceinline__ void ldsm4(uint32_t& r0, uint32_t& r1, uint32_t& r2, uint32_t& r3,
                                      uint32_t a) {
    asm volatile("ldmatrix.sync.aligned.m8n8.x4.shared.b16 {%0,%1,%2,%3}, [%4];"
                 : "=r"(r0), "=r"(r1), "=r"(r2), "=r"(r3) : "r"(a));
}
__device__ __forceinline__ void ldsm4t(uint32_t& r0, uint32_t& r1, uint32_t& r2, uint32_t& r3,
                                       uint32_t a) {
    asm volatile("ldmatrix.sync.aligned.m8n8.x4.trans.shared.b16 {%0,%1,%2,%3}, [%4];"
                 : "=r"(r0), "=r"(r1), "=r"(r2), "=r"(r3) : "r"(a));
}
__device__ __forceinline__ void cp16(uint32_t dst, const void* src) {
    asm volatile("cp.async.cg.shared.global [%0], [%1], 16;" :: "r"(dst), "l"(src));
}
__device__ __forceinline__ void cp16z(uint32_t dst, const void* src, int sz) {
    asm volatile("cp.async.cg.shared.global [%0], [%1], 16, %2;" :: "r"(dst), "l"(src), "r"(sz));
}
#define CP_COMMIT() asm volatile("cp.async.commit_group;" ::: "memory")
#define CP_WAIT(n)  asm volatile("cp.async.wait_group %0;" :: "n"(n) : "memory")

// ---------------------------------------------------------------------------
__global__ void cvt16(const float* __restrict__ in, __half* __restrict__ out, int n4) {
    int i = blockIdx.x * blockDim.x + threadIdx.x;
    if (i < n4) {
        float4 v = ((const float4*)in)[i];
        ((__half2*)out)[2 * i]     = __floats2half2_rn(v.x, v.y);
        ((__half2*)out)[2 * i + 1] = __floats2half2_rn(v.z, v.w);
    }
}

// ---------------------------------------------------------------------------
// fp16 GEMM (unchanged from R5): Y = A·Wᵀ + bias, 128x128 tile, BK=32,
// cp.async double-buffered, 256 threads.
// ---------------------------------------------------------------------------
__device__ __forceinline__ void gemm_stage(
    const __half* __restrict__ A, const __half* __restrict__ W,
    uint32_t sa, uint32_t sw, int kc, int m0, int n0, int M, int t)
{
#pragma unroll
    for (int i = 0; i < 2; i++) {
        const int id = t + i * 256;
        const int row = id >> 2, slot = id & 3;
        const int ar = m0 + row;
        const __half* asrc = A + (size_t)(ar < M ? ar : 0) * DIM + kc * 32 + slot * 8;
        cp16z(sa + (uint32_t)(row * GSTR + slot * 8) * 2, asrc, ar < M ? 16 : 0);
        cp16(sw + (uint32_t)(row * GSTR + slot * 8) * 2,
             W + (size_t)(n0 + row) * DIM + kc * 32 + slot * 8);
    }
    CP_COMMIT();
}

__global__ __launch_bounds__(256, 2) void gemm_h16(
    const __half* __restrict__ A,
    const __half* __restrict__ W0, const float* __restrict__ B0, float* __restrict__ Y0,
    const __half* __restrict__ W1, const float* __restrict__ B1, float* __restrict__ Y1,
    const __half* __restrict__ W2, const float* __restrict__ B2, float* __restrict__ Y2,
    int M)
{
    __shared__ __half SA[2][128 * GSTR];
    __shared__ __half SW[2][128 * GSTR];

    const __half* W; const float* Bi; float* Y;
    if (blockIdx.z == 0)      { W = W0; Bi = B0; Y = Y0; }
    else if (blockIdx.z == 1) { W = W1; Bi = B1; Y = Y1; }
    else                      { W = W2; Bi = B2; Y = Y2; }

    const int t = threadIdx.x, l = t & 31, wid = t >> 5;
    const int wm = (wid & 3) * 32, wn = (wid >> 2) * 64;
    const int g = l >> 2, tg = l & 3;
    const int m0 = blockIdx.x * 128, n0 = blockIdx.y * 128;

    const uint32_t saw[2] = { smem_u32(SA[0]), smem_u32(SA[1]) };
    const uint32_t sww[2] = { smem_u32(SW[0]), smem_u32(SW[1]) };

    const int a_row = (l & 7) + 8 * ((l >> 3) & 1);
    const int a_half = 8 * ((l >> 4) & 1);
    const int b_row = (l & 7) + 8 * ((l >> 4) & 1);
    const int b_half = 8 * ((l >> 3) & 1);

    float acc[2][8][4];
#pragma unroll
    for (int i = 0; i < 2; i++)
#pragma unroll
        for (int j = 0; j < 8; j++)
#pragma unroll
            for (int c = 0; c < 4; c++) acc[i][j][c] = 0.0f;

    gemm_stage(A, W, saw[0], sww[0], 0, m0, n0, M, t);

    for (int kc = 0; kc < DIM / 32; kc++) {
        const int b = kc & 1;
        if (kc + 1 < DIM / 32) {
            gemm_stage(A, W, saw[1 - b], sww[1 - b], kc + 1, m0, n0, M, t);
            CP_WAIT(1);
        } else {
            CP_WAIT(0);
        }
        __syncthreads();

        const uint32_t ab = saw[b], wb = sww[b];
#pragma unroll
        for (int ks = 0; ks < 2; ks++) {
            uint32_t af[2][4];
            ldsm4(af[0][0], af[0][1], af[0][2], af[0][3],
                  ab + (uint32_t)((wm + a_row) * GSTR + 16 * ks + a_half) * 2);
            ldsm4(af[1][0], af[1][1], af[1][2], af[1][3],
                  ab + (uint32_t)((wm + 16 + a_row) * GSTR + 16 * ks + a_half) * 2);
#pragma unroll
            for (int j = 0; j < 4; j++) {
                uint32_t b0, b1, b2, b3;
                ldsm4(b0, b1, b2, b3,
                      wb + (uint32_t)((wn + 16 * j + b_row) * GSTR + 16 * ks + b_half) * 2);
                mma16(acc[0][2 * j],     af[0], b0, b1);
                mma16(acc[0][2 * j + 1], af[0], b2, b3);
                mma16(acc[1][2 * j],     af[1], b0, b1);
                mma16(acc[1][2 * j + 1], af[1], b2, b3);
            }
        }
        __syncthreads();
    }

#pragma unroll
    for (int mt = 0; mt < 2; mt++) {
        const int r0 = m0 + wm + mt * 16 + g;
#pragma unroll
        for (int nt = 0; nt < 8; nt++) {
            const int cc = n0 + wn + nt * 8 + 2 * tg;
            const float b0 = Bi[cc], b1 = Bi[cc + 1];
            if (r0 < M) {
                float2 v = make_float2(acc[mt][nt][0] + b0, acc[mt][nt][1] + b1);
                *(float2*)&Y[(size_t)r0 * DIM + cc] = v;
            }
            if (r0 + 8 < M) {
                float2 v = make_float2(acc[mt][nt][2] + b0, acc[mt][nt][3] + b1);
                *(float2*)&Y[(size_t)(r0 + 8) * DIM + cc] = v;
            }
        }
    }
}

// ---------------------------------------------------------------------------
// RMSNorm + RoPE.  q (which=0): fp32 in place.  k (which=1): fp16 into the
// unified window buffer Ku[head][cnw + s][dim].
// ---------------------------------------------------------------------------
__global__ __launch_bounds__(256) void rmsnorm_rope(
    float* __restrict__ q, const float* __restrict__ k,
    __half* __restrict__ ku,
    const float* __restrict__ gq, const float* __restrict__ gk,
    const float* __restrict__ freqs,
    const int* __restrict__ grid_sizes,
    const int* __restrict__ cur_start_p, int S)
{
    const int s = blockIdx.x;
    const int which = blockIdx.y;
    const float* row = (which ? k : q) + (size_t)s * DIM;
    const float* g = which ? gk : gq;

    __shared__ float red[8];
    __shared__ float cs[64], sn[64];
    const int t = threadIdx.x;

    float ss = 0.0f;
#pragma unroll
    for (int i = 0; i < 6; i++) {
        const float v = row[t + i * 256];
        ss += v * v;
    }
#pragma unroll
    for (int o = 16; o; o >>= 1) ss += __shfl_xor_sync(0xffffffffu, ss, o);
    if ((t & 31) == 0) red[t >> 5] = ss;
    __syncthreads();
    if (t < 8) {
        float v = red[t];
#pragma unroll
        for (int o = 4; o; o >>= 1) v += __shfl_xor_sync(0xffu, v, o);
        if (t == 0) red[0] = v;
    }

    const int Hh = grid_sizes[1];
    const int Ww = grid_sizes[2];
    const int FHW = grid_sizes[0] * Hh * Ww;
    const bool rot = (s < FHW);
    const int cur = cur_start_p[0];
    int ws = cur + S - MAX_ATTN_W; if (ws < 0) ws = 0;
    const int cnw = cur - ws;

    if (rot && t < 64) {
        const int fs = Hh * Ww;
        const int sf = cur / fs;
        const int f = s / fs;
        const int rem = s - f * fs;
        const int h = rem / Ww;
        const int w = rem - h * Ww;
        int idx;
        if (t < 22)       idx = sf + f;
        else if (t < 43)  idx = h;
        else              idx = w;
        const float ang = freqs[idx * 64 + t];
        cs[t] = cosf(ang);
        sn[t] = sinf(ang);
    }
    __syncthreads();

    const float scale = rsqrtf(red[0] * (1.0f / DIM) + 1e-6f);

#pragma unroll
    for (int r = 0; r < 3; r++) {
        const int p = t + r * 256;
        const int j = p & 63;
        const int e0 = 2 * p, e1 = e0 + 1;
        const float a = row[e0] * scale * g[e0];
        const float b = row[e1] * scale * g[e1];
        float o0, o1;
        if (rot) {
            const float c = cs[j], s_ = sn[j];
            o0 = a * c - b * s_;
            o1 = a * s_ + b * c;
        } else {
            o0 = a; o1 = b;
        }
        if (which == 0) {
            q[(size_t)s * DIM + e0] = o0;
            q[(size_t)s * DIM + e1] = o1;
        } else {
            const int hh = e0 >> 7, d = e0 & 127;
            const uint32_t hv = pkh(o0, o1);
            *(uint32_t*)&ku[((size_t)hh * LWMAX + cnw + s) * HD + d] = hv;
        }
    }
}

// ---------------------------------------------------------------------------
// Materialize fp16 window KV.  K: cache part [0,cnw) + zero pad [Lw,ceil64).
// V: cache part + new part + pad.  grid = (LWMAX/64, NH), 256 threads.
// ---------------------------------------------------------------------------
__global__ __launch_bounds__(256) void fill_kv(
    const float* __restrict__ kcache, const float* __restrict__ vcache,
    const float* __restrict__ vnew,
    __half* __restrict__ ku, __half* __restrict__ vu,
    const int* __restrict__ cur_start_p, int S)
{
    const int hh = blockIdx.y;
    const int wt = blockIdx.x;
    const int t = threadIdx.x;

    const int cur = cur_start_p[0];
    int ws = cur + S - MAX_ATTN_W; if (ws < 0) ws = 0;
    const int cnw = cur - ws;
    const int Lw = cur + S - ws;
    const int Lpad = (Lw + 63) & ~63;
    if (wt * 64 >= Lpad) return;

#pragma unroll
    for (int i = 0; i < 8; i++) {
        const int idx = t + i * 256;
        const int tok = idx >> 5;
        const int d4 = (idx & 31) * 4;
        const int w = wt * 64 + tok;

        // K
        if (w < cnw) {
            const float4 v = *(const float4*)&kcache[((size_t)(ws + w) * NH + hh) * HD + d4];
            uint2 u; u.x = pkh(v.x, v.y); u.y = pkh(v.z, v.w);
            *(uint2*)&ku[((size_t)hh * LWMAX + w) * HD + d4] = u;
        } else if (w >= Lw) {
            uint2 u; u.x = 0u; u.y = 0u;
            *(uint2*)&ku[((size_t)hh * LWMAX + w) * HD + d4] = u;
        }
        // V
        float4 vv = make_float4(0.f, 0.f, 0.f, 0.f);
        if (w < cnw)     vv = *(const float4*)&vcache[((size_t)(ws + w) * NH + hh) * HD + d4];
        else if (w < Lw) vv = *(const float4*)&vnew[(size_t)(w - cnw) * DIM + hh * HD + d4];
        uint2 u; u.x = pkh(vv.x, vv.y); u.y = pkh(vv.z, vv.w);
        *(uint2*)&vu[((size_t)hh * LWMAX + w) * HD + d4] = u;
    }
}

// ---------------------------------------------------------------------------
// fp16 flash attention with cp.async double-buffered KV tiles.
// 4 warps x 16 q-rows, 64-key tiles.  P in registers.  fp16 output.
// smem (halfs): K0 @0, K1 @ABUF, V0 @2*ABUF, V1 @3*ABUF.
// ---------------------------------------------------------------------------
__device__ __forceinline__ void attn_stage(
    const __half* __restrict__ ksrc, const __half* __restrict__ vsrc,
    uint32_t kw, uint32_t vw, int kb, int t)
{
#pragma unroll
    for (int i = 0; i < 8; i++) {
        const int id = t + i * 128;
        const int r = id >> 4, c = id & 15;
        cp16(kw + (uint32_t)(r * ASTR + c * 8) * 2, ksrc + (size_t)(kb + r) * HD + c * 8);
        cp16(vw + (uint32_t)(r * ASTR + c * 8) * 2, vsrc + (size_t)(kb + r) * HD + c * 8);
    }
    CP_COMMIT();
}

__global__ __launch_bounds__(128, 2) void attn_h16(
    const float* __restrict__ q,
    const __half* __restrict__ ku, const __half* __restrict__ vu,
    __half* __restrict__ o16,
    const int* __restrict__ cur_start_p, int S)
{
    extern __shared__ __half sma[];
    const int hh = blockIdx.y;
    const int q0 = blockIdx.x * 64;
    const int t = threadIdx.x, l = t & 31, wid = t >> 5;
    const int g = l >> 2, tg = l & 3;

    const int cur = cur_start_p[0];
    const int cur_end = cur + S;
    int ws = cur_end - MAX_ATTN_W; if (ws < 0) ws = 0;
    const int Lw = cur_end - ws;
    const int ntiles = (Lw + 63) >> 6;

    const __half* ksrc = ku + (size_t)hh * LWMAX * HD;
    const __half* vsrc = vu + (size_t)hh * LWMAX * HD;

    const uint32_t sb = smem_u32(sma);
    const uint32_t kwb[2] = { sb, sb + ABUF * 2u };
    const uint32_t vwb[2] = { sb + 2u * ABUF * 2u, sb + 3u * ABUF * 2u };

    const int k_row = (l & 7) + ((l >> 4) & 1) * 8;
    const int k_half = ((l >> 3) & 1) * 8;
    const int v_row = (l & 7) + ((l >> 3) & 1) * 8;
    const int v_dim = ((l >> 4) & 1) * 8;

    // Q A-fragments (fp32 -> fp16 once)
    const int row0 = q0 + wid * 16 + g;
    const bool r0ok = row0 < S, r1ok = (row0 + 8) < S;
    uint32_t qa[8][4];
    {
        const float2* qp0 = (const float2*)(q + (size_t)(r0ok ? row0 : 0) * DIM + hh * HD);
        const float2* qp1 = (const float2*)(q + (size_t)(r1ok ? row0 + 8 : 0) * DIM + hh * HD);
#pragma unroll
        for (int ks = 0; ks < 8; ks++) {
            float2 x0 = qp0[8 * ks + tg],     x1 = qp1[8 * ks + tg];
            float2 x2 = qp0[8 * ks + tg + 4], x3 = qp1[8 * ks + tg + 4];
            qa[ks][0] = r0ok ? pkh(x0.x, x0.y) : 0u;
            qa[ks][1] = r1ok ? pkh(x1.x, x1.y) : 0u;
            qa[ks][2] = r0ok ? pkh(x2.x, x2.y) : 0u;
            qa[ks][3] = r1ok ? pkh(x3.x, x3.y) : 0u;
        }
    }

    float o_acc[16][4];
#pragma unroll
    for (int nt = 0; nt < 16; nt++)
#pragma unroll
        for (int c = 0; c < 4; c++) o_acc[nt][c] = 0.0f;
    float mA = -1e30f, mB = -1e30f, lA = 0.0f, lB = 0.0f;
    const float sc = 0.08838834764831845f;

    attn_stage(ksrc, vsrc, kwb[0], vwb[0], 0, t);

    for (int tile = 0; tile < ntiles; tile++) {
        const int b = tile & 1;
        if (tile + 1 < ntiles) {
            attn_stage(ksrc, vsrc, kwb[1 - b], vwb[1 - b], (tile + 1) * 64, t);
            CP_WAIT(1);
        } else {
            CP_WAIT(0);
        }
        __syncthreads();

        const uint32_t ksb = kwb[b], vsb = vwb[b];

        // S = Q K^T
        float s_acc[8][4];
#pragma unroll
        for (int nt = 0; nt < 8; nt++)
#pragma unroll
            for (int c = 0; c < 4; c++) s_acc[nt][c] = 0.0f;
#pragma unroll
        for (int ks = 0; ks < 8; ks++) {
#pragma unroll
            for (int j = 0; j < 4; j++) {
                uint32_t b0, b1, b2, b3;
                ldsm4(b0, b1, b2, b3,
                      ksb + (uint32_t)((16 * j + k_row) * ASTR + 16 * ks + k_half) * 2);
                mma16(s_acc[2 * j],     qa[ks], b0, b1);
                mma16(s_acc[2 * j + 1], qa[ks], b2, b3);
            }
        }

        // scale + mask
        const int kb = tile * 64;
#pragma unroll
        for (int nt = 0; nt < 8; nt++) {
            const int key0 = kb + nt * 8 + 2 * tg;
            const bool ok0 = key0 < Lw, ok1 = (key0 + 1) < Lw;
            s_acc[nt][0] = ok0 ? s_acc[nt][0] * sc : -1e30f;
            s_acc[nt][1] = ok1 ? s_acc[nt][1] * sc : -1e30f;
            s_acc[nt][2] = ok0 ? s_acc[nt][2] * sc : -1e30f;
            s_acc[nt][3] = ok1 ? s_acc[nt][3] * sc : -1e30f;
        }

        // online softmax
        float rmA = -1e30f, rmB = -1e30f;
#pragma unroll
        for (int nt = 0; nt < 8; nt++) {
            rmA = fmaxf(rmA, fmaxf(s_acc[nt][0], s_acc[nt][1]));
            rmB = fmaxf(rmB, fmaxf(s_acc[nt][2], s_acc[nt][3]));
        }
        rmA = fmaxf(rmA, __shfl_xor_sync(0xffffffffu, rmA, 1));
        rmA = fmaxf(rmA, __shfl_xor_sync(0xffffffffu, rmA, 2));
        rmB = fmaxf(rmB, __shfl_xor_sync(0xffffffffu, rmB, 1));
        rmB = fmaxf(rmB, __shfl_xor_sync(0xffffffffu, rmB, 2));
        const float nmA = fmaxf(mA, rmA), nmB = fmaxf(mB, rmB);
        const float aA = __expf(mA - nmA), aB = __expf(mB - nmB);
        mA = nmA; mB = nmB;

        float suA = 0.0f, suB = 0.0f;
#pragma unroll
        for (int nt = 0; nt < 8; nt++) {
            s_acc[nt][0] = __expf(s_acc[nt][0] - nmA);
            s_acc[nt][1] = __expf(s_acc[nt][1] - nmA);
            s_acc[nt][2] = __expf(s_acc[nt][2] - nmB);
            s_acc[nt][3] = __expf(s_acc[nt][3] - nmB);
            suA += s_acc[nt][0] + s_acc[nt][1];
            suB += s_acc[nt][2] + s_acc[nt][3];
        }
        suA += __shfl_xor_sync(0xffffffffu, suA, 1);
        suA += __shfl_xor_sync(0xffffffffu, suA, 2);
        suB += __shfl_xor_sync(0xffffffffu, suB, 1);
        suB += __shfl_xor_sync(0xffffffffu, suB, 2);
        lA = lA * aA + suA;
        lB = lB * aB + suB;

#pragma unroll
        for (int nt = 0; nt < 16; nt++) {
            o_acc[nt][0] *= aA; o_acc[nt][1] *= aA;
            o_acc[nt][2] *= aB; o_acc[nt][3] *= aB;
        }

        // O += P V  (A-fragments from registers)
#pragma unroll
        for (int ks = 0; ks < 4; ks++) {
            uint32_t ap[4];
            ap[0] = pkh(s_acc[2 * ks][0],     s_acc[2 * ks][1]);
            ap[1] = pkh(s_acc[2 * ks][2],     s_acc[2 * ks][3]);
            ap[2] = pkh(s_acc[2 * ks + 1][0], s_acc[2 * ks + 1][1]);
            ap[3] = pkh(s_acc[2 * ks + 1][2], s_acc[2 * ks + 1][3]);
#pragma unroll
            for (int j = 0; j < 8; j++) {
                uint32_t b0, b1, b2, b3;
                ldsm4t(b0, b1, b2, b3,
                       vsb + (uint32_t)((16 * ks + v_row) * ASTR + 16 * j + v_dim) * 2);
                mma16(o_acc[2 * j],     ap, b0, b1);
                mma16(o_acc[2 * j + 1], ap, b2, b3);
            }
        }
        __syncthreads();
    }

    const float iA = 1.0f / lA, iB = 1.0f / lB;
#pragma unroll
    for (int nt = 0; nt < 16; nt++) {
        const int cc = hh * HD + nt * 8 + 2 * tg;
        if (r0ok)
            *(uint32_t*)&o16[(size_t)row0 * DIM + cc] = pkh(o_acc[nt][0] * iA, o_acc[nt][1] * iA);
        if (r1ok)
            *(uint32_t*)&o16[(size_t)(row0 + 8) * DIM + cc] = pkh(o_acc[nt][2] * iB, o_acc[nt][3] * iB);
    }
}

// ---------------------------------------------------------------------------
extern "C" void kernel_launch(void* const* d_in, const int* in_sizes, int n_in,
                              void* d_out, int out_size)
{
    const float* x      = (const float*)d_in[0];
    const float* freqs  = (const float*)d_in[1];
    const float* wq     = (const float*)d_in[2];
    const float* bq     = (const float*)d_in[3];
    const float* wk     = (const float*)d_in[4];
    const float* bk     = (const float*)d_in[5];
    const float* wv     = (const float*)d_in[6];
    const float* bv     = (const float*)d_in[7];
    const float* wo     = (const float*)d_in[8];
    const float* bo     = (const float*)d_in[9];
    const float* gq     = (const float*)d_in[10];
    const float* gk     = (const float*)d_in[11];
    const float* kcache = (const float*)d_in[12];
    const float* vcache = (const float*)d_in[13];
    const int* grid_sizes = (const int*)d_in[14];
    const int* cur_start  = (const int*)d_in[16];

    const int S = in_sizes[0] / DIM;

    float *q, *k, *v;
    __half *x16, *o16, *wq16, *wk16, *wv16, *wo16, *ku, *vu;
    cudaGetSymbolAddress((void**)&q, g_q);
    cudaGetSymbolAddress((void**)&k, g_k);
    cudaGetSymbolAddress((void**)&v, g_v);
    cudaGetSymbolAddress((void**)&x16, g_x16);
    cudaGetSymbolAddress((void**)&o16, g_o16);
    cudaGetSymbolAddress((void**)&wq16, g_wq16);
    cudaGetSymbolAddress((void**)&wk16, g_wk16);
    cudaGetSymbolAddress((void**)&wv16, g_wv16);
    cudaGetSymbolAddress((void**)&wo16, g_wo16);
    cudaGetSymbolAddress((void**)&ku, g_ku);
    cudaGetSymbolAddress((void**)&vu, g_vu);

    const int wn4 = DIM * DIM / 4;
    const int xn4 = S * DIM / 4;
    cvt16<<<(xn4 + 255) / 256, 256>>>(x, x16, xn4);
    cvt16<<<(wn4 + 255) / 256, 256>>>(wq, wq16, wn4);
    cvt16<<<(wn4 + 255) / 256, 256>>>(wk, wk16, wn4);
    cvt16<<<(wn4 + 255) / 256, 256>>>(wv, wv16, wn4);
    cvt16<<<(wn4 + 255) / 256, 256>>>(wo, wo16, wn4);

    // fused QKV projections
    gemm_h16<<<dim3((S + 127) / 128, DIM / 128, 3), 256>>>(
        x16, wq16, bq, q, wk16, bk, k, wv16, bv, v, S);

    // RMSNorm + RoPE (k -> fp16 window buffer), then materialize cache KV
    rmsnorm_rope<<<dim3(S, 2), 256>>>(q, k, ku, gq, gk, freqs, grid_sizes, cur_start, S);
    fill_kv<<<dim3(LWMAX / 64, NH), 256>>>(kcache, vcache, v, ku, vu, cur_start, S);

    const int asmem = 4 * ABUF * 2;   // 69632 B
    cudaFuncSetAttribute(attn_h16, cudaFuncAttributeMaxDynamicSharedMemorySize, asmem);
    attn_h16<<<dim3((S + 63) / 64, NH), 128, asmem>>>(q, ku, vu, o16, cur_start, S);

    // output projection
    gemm_h16<<<dim3((S + 127) / 128, DIM / 128, 1), 256>>>(
        o16, wo16, bo, (float*)d_out, wo16, bo, (float*)d_out, wo16, bo, (float*)d_out, S);
}